// round 1
// baseline (speedup 1.0000x reference)
#include <cuda_runtime.h>
#include <cuda_bf16.h>
#include <math.h>

// ---------------- problem constants ----------------
#define BATCH   2
#define CDIM    512
#define C3      1536
#define HH      128
#define WW      128
#define HW      16384           // 128*128
#define HEADS   64
#define CH      8               // channels per head
#define EPSN    1e-12f
#define EPSBN   1e-5f

// ---------------- scratch (device globals; no runtime alloc allowed) -------
// qkv intermediate (reused for both modalities sequentially): [B][C3][HW]
__device__ float g_qkv[BATCH * C3 * HW];                 // 192 MB
// post-dwconv q/k/v for each modality: [mod][B][C3][HW]
__device__ float g_dw[2][BATCH * C3 * HW];               // 384 MB
// attention scores attn1/attn2: [attn][B][HEADS][CH][CH]
__device__ float g_attn[2 * BATCH * HEADS * CH * CH];
// softmaxed weights a1/a2: same layout
__device__ float g_aw[2 * BATCH * HEADS * CH * CH];

// ---------------- Kernel 1: qkv 1x1 conv == GEMM ----------------
// y[b][co][p] = bias[co] + sum_ci w[co][ci] * x[b][ci][p]
// Block tile: 128 positions (M) x 64 out-channels (N), BK=16.
// Per-thread 8x4 tile held as 4 packed f32x2 accumulators; fma.rn.f32x2 doubles
// fp32 FMA throughput on sm_103a while remaining exact fp32.
__global__ void __launch_bounds__(256) qkv_gemm_kernel(
    const float* __restrict__ x, const float* __restrict__ w,
    const float* __restrict__ bias)
{
    __shared__ float As[16][128];
    __shared__ float Bs[16][65];

    const int b  = blockIdx.z;
    const int p0 = blockIdx.x * 128;
    const int n0 = blockIdx.y * 64;
    const int tid = threadIdx.x;
    const int tx = tid & 15;      // N direction (4 cols each)
    const int ty = tid >> 4;      // M direction (8 rows each, as 4 pairs)

    const float* xb = x + (size_t)b * CDIM * HW + p0;

    unsigned long long acc[4][4];
#pragma unroll
    for (int i = 0; i < 4; ++i)
#pragma unroll
        for (int j = 0; j < 4; ++j) acc[i][j] = 0ull;

    for (int k0 = 0; k0 < CDIM; k0 += 16) {
        // load A tile: 16 x 128 floats, float4, fully coalesced
#pragma unroll
        for (int it = 0; it < 2; ++it) {
            int s  = tid + it * 256;      // float4 slot 0..511
            int k  = s >> 5;
            int m4 = s & 31;
            float4 v = *(const float4*)(xb + (size_t)(k0 + k) * HW + m4 * 4);
            *(float4*)&As[k][m4 * 4] = v;
        }
        // load B tile: 16 x 64 floats (w rows contiguous along k)
#pragma unroll
        for (int it = 0; it < 4; ++it) {
            int k = tid & 15;
            int n = (tid >> 4) + it * 16;
            Bs[k][n] = w[(size_t)(n0 + n) * CDIM + k0 + k];
        }
        __syncthreads();

#pragma unroll
        for (int kk = 0; kk < 16; ++kk) {
            unsigned long long a2[4];
            const unsigned long long* ap =
                (const unsigned long long*)&As[kk][ty * 8];
            a2[0] = ap[0]; a2[1] = ap[1]; a2[2] = ap[2]; a2[3] = ap[3];
#pragma unroll
            for (int j = 0; j < 4; ++j) {
                float bv = Bs[kk][tx * 4 + j];
                unsigned long long b2;
                asm("mov.b64 %0, {%1, %1};" : "=l"(b2) : "r"(__float_as_uint(bv)));
#pragma unroll
                for (int i = 0; i < 4; ++i)
                    asm("fma.rn.f32x2 %0, %1, %2, %0;"
                        : "+l"(acc[i][j]) : "l"(a2[i]), "l"(b2));
            }
        }
        __syncthreads();
    }

    // epilogue: add bias, write coalesced float4 pairs
#pragma unroll
    for (int j = 0; j < 4; ++j) {
        int co = n0 + tx * 4 + j;
        float bv = bias[co];
        float o[8];
#pragma unroll
        for (int i = 0; i < 4; ++i) {
            unsigned lo, hi;
            asm("mov.b64 {%0,%1}, %2;" : "=r"(lo), "=r"(hi) : "l"(acc[i][j]));
            o[2 * i]     = __uint_as_float(lo) + bv;
            o[2 * i + 1] = __uint_as_float(hi) + bv;
        }
        float* yp = g_qkv + (size_t)b * C3 * HW + (size_t)co * HW + p0 + ty * 8;
        *(float4*)yp       = make_float4(o[0], o[1], o[2], o[3]);
        *((float4*)yp + 1) = make_float4(o[4], o[5], o[6], o[7]);
    }
}

// ---------------- Kernel 2: depthwise 3x3, SAME (zero pad) ----------------
__global__ void __launch_bounds__(256) dwconv_kernel(
    const float* __restrict__ w, const float* __restrict__ bias, int mod)
{
    const int c = blockIdx.y;
    const int b = blockIdx.z;
    const int p = blockIdx.x * 256 + threadIdx.x;
    const int i = p >> 7;
    const int j = p & 127;

    const float* xc = g_qkv + ((size_t)b * C3 + c) * HW;
    float wv[9];
#pragma unroll
    for (int t = 0; t < 9; ++t) wv[t] = __ldg(w + c * 9 + t);

    float acc = __ldg(bias + c);
#pragma unroll
    for (int dy = -1; dy <= 1; ++dy) {
        int ii = i + dy;
        if ((unsigned)ii < 128u) {
#pragma unroll
            for (int dx = -1; dx <= 1; ++dx) {
                int jj = j + dx;
                if ((unsigned)jj < 128u)
                    acc += wv[(dy + 1) * 3 + dx + 1] * __ldg(xc + ii * 128 + jj);
            }
        }
    }
    g_dw[mod][((size_t)b * C3 + c) * HW + p] = acc;
}

// ---------------- Kernel 3: channel attention scores + l2 norms ------------
// One block per (head, batch). tensors: 0=hq 1=lk 2=lq 3=hk
// attn1 = <hq_c, lk_d>/(|hq_c||lk_d|) * temp1[h]; attn2 with (lq, hk, temp2)
__global__ void __launch_bounds__(256) attn_kernel(
    const float* __restrict__ temp1, const float* __restrict__ temp2)
{
    const int h = blockIdx.x;
    const int b = blockIdx.y;
    const int t = threadIdx.x;

    __shared__ float tile[4][8][132];
    __shared__ float red[256];
    __shared__ float invn[4][8];

    const size_t base = (size_t)b * C3 * HW + (size_t)h * CH * HW;
    const float* t_hq = g_dw[0] + base;
    const float* t_lk = g_dw[1] + base + (size_t)CDIM * HW;
    const float* t_lq = g_dw[1] + base;
    const float* t_hk = g_dw[0] + base + (size_t)CDIM * HW;

    const int pairattn = t & 127;
    const int jp   = t >> 7;
    const int attn = pairattn >> 6;
    const int c    = (pairattn >> 3) & 7;
    const int d    = pairattn & 7;

    float acc = 0.f;
    float sq  = 0.f;
    const int col = t & 127;
    const int r0  = t >> 7;

    for (int n0 = 0; n0 < HW; n0 += 128) {
        // cooperative load: 4 tensors x 8 rows x 128 cols, coalesced
#pragma unroll
        for (int it = 0; it < 16; ++it) {
            const int tens = it >> 2;
            const int row  = (r0 + 2 * it) & 7;
            const float* src = (tens == 0) ? t_hq : (tens == 1) ? t_lk
                             : (tens == 2) ? t_lq : t_hk;
            tile[tens][row][col] = __ldg(src + (size_t)row * HW + n0 + col);
        }
        __syncthreads();

        const float* qrow = &tile[attn * 2][c][0];
        const float* krow = &tile[attn * 2 + 1][d][0];
#pragma unroll 8
        for (int jj = jp * 64; jj < jp * 64 + 64; ++jj)
            acc += qrow[jj] * krow[jj];

        if (t < 32) {  // sum of squares for all 32 rows (norms)
            const float* rr = &tile[t >> 3][t & 7][0];
#pragma unroll 8
            for (int jj = 0; jj < 128; ++jj) sq += rr[jj] * rr[jj];
        }
        __syncthreads();
    }

    red[t] = acc;
    __syncthreads();
    if (t < 32) {
        float nrm = sqrtf(sq);
        invn[t >> 3][t & 7] = 1.f / fmaxf(nrm, EPSN);
    }
    __syncthreads();
    if (t < 128) {
        float dot = red[t] + red[t + 128];
        float tmp = (attn == 0) ? __ldg(temp1 + h) : __ldg(temp2 + h);
        float scale = invn[attn * 2][c] * invn[attn * 2 + 1][d] * tmp;
        g_attn[(((size_t)attn * BATCH + b) * HEADS + h) * 64 + c * 8 + d] = dot * scale;
    }
}

// ---------------- Kernel 4: conv fusion + BN + ReLU + softmax --------------
__global__ void __launch_bounds__(512) fuse_kernel(
    const float* __restrict__ pw, const float* __restrict__ pb,
    const float* __restrict__ gamma, const float* __restrict__ beta,
    const float* __restrict__ mean, const float* __restrict__ var)
{
    const int b = blockIdx.x;
    const int t = threadIdx.x;
    __shared__ float a1s[HEADS * 64];
    __shared__ float a2s[HEADS * 64];

#pragma unroll
    for (int it = 0; it < 8; ++it) {
        int idx = t + it * 512;
        a1s[idx] = g_attn[(size_t)b * 4096 + idx];
        a2s[idx] = g_attn[((size_t)BATCH + b) * 4096 + idx];
    }
    __syncthreads();

    const int ho = t >> 3;
    const int c  = t & 7;
    float f[8] = {0, 0, 0, 0, 0, 0, 0, 0};
    for (int hi = 0; hi < 64; ++hi) {
        float w1 = __ldg(pw + ho * 128 + hi);
        float w2 = __ldg(pw + ho * 128 + 64 + hi);
#pragma unroll
        for (int dd = 0; dd < 8; ++dd) {
            f[dd] += w1 * a1s[hi * 64 + c * 8 + dd];
            f[dd] += w2 * a2s[hi * 64 + c * 8 + dd];
        }
    }
    const float inv_std = rsqrtf(__ldg(var + ho) + EPSBN);
    const float g = __ldg(gamma + ho), bb = __ldg(beta + ho);
    const float mu = __ldg(mean + ho), pbi = __ldg(pb + ho);
#pragma unroll
    for (int dd = 0; dd < 8; ++dd)
        f[dd] = fmaxf((f[dd] + pbi - mu) * inv_std * g + bb, 0.f);

    // softmax(fused + attnX) over d, for both attn branches
#pragma unroll
    for (int which = 0; which < 2; ++which) {
        const float* as = which ? a2s : a1s;
        float s[8], mx = -1e30f;
#pragma unroll
        for (int dd = 0; dd < 8; ++dd) {
            s[dd] = f[dd] + as[ho * 64 + c * 8 + dd];
            mx = fmaxf(mx, s[dd]);
        }
        float sum = 0.f;
#pragma unroll
        for (int dd = 0; dd < 8; ++dd) { s[dd] = expf(s[dd] - mx); sum += s[dd]; }
        float inv = 1.f / sum;
#pragma unroll
        for (int dd = 0; dd < 8; ++dd)
            g_aw[((size_t)which * BATCH + b) * 4096 + t * 8 + dd] = s[dd] * inv;
    }
}

// ---------------- Kernel 5: output einsum + residuals ----------------------
// out[c,n] = x_in[c,n] + v[c,n] + sum_d a[c,d] * v[d,n]
__global__ void __launch_bounds__(256) out_kernel(
    const float* __restrict__ hsi, const float* __restrict__ lidar,
    float* __restrict__ out)
{
    const int h   = blockIdx.y;
    const int zz  = blockIdx.z;
    const int mod = zz >> 1;
    const int b   = zz & 1;
    const int t   = threadIdx.x;

    __shared__ float aw[64];
    if (t < 64)
        aw[t] = g_aw[(((size_t)mod * BATCH + b) * HEADS + h) * 64 + t];
    __syncthreads();

    const float* vsrc = g_dw[mod] + ((size_t)b * C3 + 2 * CDIM + h * CH) * HW;
    const float* xin  = (mod ? lidar : hsi) + ((size_t)b * CDIM + h * CH) * HW;
    float* o = out + (size_t)mod * BATCH * CDIM * HW + ((size_t)b * CDIM + h * CH) * HW;

    const int n = blockIdx.x * 256 + t;
    float v[8];
#pragma unroll
    for (int dd = 0; dd < 8; ++dd) v[dd] = __ldg(vsrc + (size_t)dd * HW + n);

#pragma unroll
    for (int c = 0; c < 8; ++c) {
        float s = __ldg(xin + (size_t)c * HW + n) + v[c];
#pragma unroll
        for (int dd = 0; dd < 8; ++dd) s += aw[c * 8 + dd] * v[dd];
        o[(size_t)c * HW + n] = s;
    }
}

// ---------------- launch ----------------
extern "C" void kernel_launch(void* const* d_in, const int* in_sizes, int n_in,
                              void* d_out, int out_size)
{
    const float* hsi        = (const float*)d_in[0];
    const float* lidar      = (const float*)d_in[1];
    const float* hsi_qkv_w  = (const float*)d_in[2];
    const float* hsi_qkv_b  = (const float*)d_in[3];
    const float* lidar_qkv_w= (const float*)d_in[4];
    const float* lidar_qkv_b= (const float*)d_in[5];
    const float* hsi_dw_w   = (const float*)d_in[6];
    const float* hsi_dw_b   = (const float*)d_in[7];
    const float* lidar_dw_w = (const float*)d_in[8];
    const float* lidar_dw_b = (const float*)d_in[9];
    const float* temp1      = (const float*)d_in[10];
    const float* temp2      = (const float*)d_in[11];
    const float* proj_w     = (const float*)d_in[12];
    const float* proj_b     = (const float*)d_in[13];
    const float* bn_gamma   = (const float*)d_in[14];
    const float* bn_beta    = (const float*)d_in[15];
    const float* bn_mean    = (const float*)d_in[16];
    const float* bn_var     = (const float*)d_in[17];
    float* out = (float*)d_out;

    dim3 ggrid(HW / 128, C3 / 64, BATCH);
    dim3 dgrid(HW / 256, C3, BATCH);

    // modality 0 (hsi): qkv gemm -> dwconv
    qkv_gemm_kernel<<<ggrid, 256>>>(hsi, hsi_qkv_w, hsi_qkv_b);
    dwconv_kernel<<<dgrid, 256>>>(hsi_dw_w, hsi_dw_b, 0);
    // modality 1 (lidar)
    qkv_gemm_kernel<<<ggrid, 256>>>(lidar, lidar_qkv_w, lidar_qkv_b);
    dwconv_kernel<<<dgrid, 256>>>(lidar_dw_w, lidar_dw_b, 1);

    attn_kernel<<<dim3(HEADS, BATCH), 256>>>(temp1, temp2);
    fuse_kernel<<<BATCH, 512>>>(proj_w, proj_b, bn_gamma, bn_beta, bn_mean, bn_var);
    out_kernel<<<dim3(HW / 256, HEADS, BATCH * 2), 256>>>(hsi, lidar, out);
}

// round 4
// speedup vs baseline: 2.5363x; 2.5363x over previous
#include <cuda_runtime.h>
#include <cuda_bf16.h>
#include <cstdint>
#include <math.h>

// ---------------- problem constants ----------------
#define BATCH   2
#define CDIM    512
#define C3      1536
#define HW      16384
#define HEADS   64
#define CH      8
#define EPSN    1e-12f
#define EPSBN   1e-5f

// ---------------- scratch ----------------
__device__ float g_qkv[BATCH * C3 * HW];                 // qkv conv out (per modality)
__device__ float g_dw[2][BATCH * C3 * HW];               // post-dwconv q/k/v
__device__ float g_part[8 * BATCH * HEADS * 160];        // partial dots(128)+sq(32)
__device__ float g_attn[2 * BATCH * HEADS * CH * CH];
__device__ float g_aw[2 * BATCH * HEADS * CH * CH];
__device__ __nv_bfloat16 g_wh[C3 * CDIM], g_wl[C3 * CDIM];
__device__ __nv_bfloat16 g_xh[BATCH * CDIM * HW], g_xl[BATCH * CDIM * HW];

// ---------------- PTX helpers (sm_80-era, valid on plain sm_103 target) -----
__device__ __forceinline__ uint32_t smem_u32(const void* p) {
    uint32_t a;
    asm("{ .reg .u64 t; cvta.to.shared.u64 t, %1; cvt.u32.u64 %0, t; }" : "=r"(a) : "l"(p));
    return a;
}
__device__ __forceinline__ void cpasync16(uint32_t saddr, const void* g) {
    asm volatile("cp.async.cg.shared.global [%0], [%1], 16;" :: "r"(saddr), "l"(g));
}
__device__ __forceinline__ void ldsm4(uint32_t addr, uint32_t* r) {
    asm volatile("ldmatrix.sync.aligned.m8n8.x4.shared.b16 {%0,%1,%2,%3}, [%4];"
        : "=r"(r[0]), "=r"(r[1]), "=r"(r[2]), "=r"(r[3]) : "r"(addr));
}
__device__ __forceinline__ void ldsm4t(uint32_t addr, uint32_t* r) {
    asm volatile("ldmatrix.sync.aligned.m8n8.x4.trans.shared.b16 {%0,%1,%2,%3}, [%4];"
        : "=r"(r[0]), "=r"(r[1]), "=r"(r[2]), "=r"(r[3]) : "r"(addr));
}
__device__ __forceinline__ void mma16816(float* c, const uint32_t* a, const uint32_t* b) {
    asm volatile("mma.sync.aligned.m16n8k16.row.col.f32.bf16.bf16.f32 "
        "{%0,%1,%2,%3}, {%4,%5,%6,%7}, {%8,%9}, {%0,%1,%2,%3};"
        : "+f"(c[0]), "+f"(c[1]), "+f"(c[2]), "+f"(c[3])
        : "r"(a[0]), "r"(a[1]), "r"(a[2]), "r"(a[3]), "r"(b[0]), "r"(b[1]));
}

// ---------------- Kernel 0: fp32 -> bf16 hi/lo split ----------------
__global__ void __launch_bounds__(256) cvt_split_kernel(
    const float* __restrict__ src, __nv_bfloat16* __restrict__ dh,
    __nv_bfloat16* __restrict__ dl, int n4)
{
    int i = blockIdx.x * 256 + threadIdx.x;
    if (i >= n4) return;
    float4 v = ((const float4*)src)[i];
    float vv[4] = {v.x, v.y, v.z, v.w};
    __nv_bfloat16 h[4], l[4];
#pragma unroll
    for (int j = 0; j < 4; ++j) {
        h[j] = __float2bfloat16_rn(vv[j]);
        l[j] = __float2bfloat16_rn(vv[j] - __bfloat162float(h[j]));
    }
    ((uint2*)dh)[i] = *(uint2*)h;
    ((uint2*)dl)[i] = *(uint2*)l;
}

// ---------------- Kernel 1: qkv 1x1 conv GEMM via mma.sync bf16 3-product ---
// y[b][m][n] = bias[m] + sum_k w[m][k] x[b][k][n]
// CTA 128(M) x 128(N), BK=32, double-buffered cp.async, 8 warps (2m x 4n).
// smem layout (bytes): A row stride 80 (64 data + pad), B row stride 272.
#define SM_A_STAGE 20480          // (Ah+Al) per stage = 2*128*80
#define SM_A_TILE  10240
#define SM_B_BASE  40960
#define SM_B_STAGE 17408          // (Bh+Bl) per stage = 2*32*272
#define SM_B_TILE  8704
#define GEMM_SMEM  75776

__device__ __forceinline__ void gemm_load_stage(
    uint32_t sb, int s, int k0,
    const __nv_bfloat16* wph, const __nv_bfloat16* wpl,
    const __nv_bfloat16* xph, const __nv_bfloat16* xpl, int tid)
{
    uint32_t a_h = sb + s * SM_A_STAGE, a_l = a_h + SM_A_TILE;
    uint32_t b_h = sb + SM_B_BASE + s * SM_B_STAGE, b_l = b_h + SM_B_TILE;
#pragma unroll
    for (int it = 0; it < 2; ++it) {
        int cid = tid + it * 256;
        int r = cid >> 2, c = cid & 3;
        uint32_t soff = r * 80 + c * 16;
        cpasync16(a_h + soff, wph + (size_t)r * CDIM + k0 + c * 8);
        cpasync16(a_l + soff, wpl + (size_t)r * CDIM + k0 + c * 8);
    }
#pragma unroll
    for (int it = 0; it < 2; ++it) {
        int cid = tid + it * 256;
        int r = cid >> 4, c = cid & 15;
        uint32_t soff = r * 272 + c * 16;
        cpasync16(b_h + soff, xph + (size_t)(k0 + r) * HW + c * 8);
        cpasync16(b_l + soff, xpl + (size_t)(k0 + r) * HW + c * 8);
    }
    asm volatile("cp.async.commit_group;");
}

__global__ void __launch_bounds__(256, 1) qkv_gemm_mma(
    const float* __restrict__ bias)
{
    extern __shared__ char smem[];
    const uint32_t sb = smem_u32(smem);
    const int tid = threadIdx.x;
    const int warp = tid >> 5, lid = tid & 31;
    const int n0 = blockIdx.x * 128;
    const int m0 = blockIdx.y * 128;
    const int b  = blockIdx.z;

    const __nv_bfloat16* wph = g_wh + (size_t)m0 * CDIM;
    const __nv_bfloat16* wpl = g_wl + (size_t)m0 * CDIM;
    const __nv_bfloat16* xph = g_xh + (size_t)b * CDIM * HW + n0;
    const __nv_bfloat16* xpl = g_xl + (size_t)b * CDIM * HW + n0;

    float acc[4][4][4];
#pragma unroll
    for (int i = 0; i < 4; ++i)
#pragma unroll
        for (int j = 0; j < 4; ++j)
#pragma unroll
            for (int q = 0; q < 4; ++q) acc[i][j][q] = 0.f;

    const int wm = (warp & 1) * 64;
    const int wn = (warp >> 1) * 32;

    gemm_load_stage(sb, 0, 0, wph, wpl, xph, xpl, tid);

    for (int ks = 0; ks < 16; ++ks) {
        const int s = ks & 1;
        if (ks + 1 < 16) {
            gemm_load_stage(sb, s ^ 1, (ks + 1) * 32, wph, wpl, xph, xpl, tid);
            asm volatile("cp.async.wait_group 1;");
        } else {
            asm volatile("cp.async.wait_group 0;");
        }
        __syncthreads();

        uint32_t a_h = sb + s * SM_A_STAGE, a_l = a_h + SM_A_TILE;
        uint32_t b_h = sb + SM_B_BASE + s * SM_B_STAGE, b_l = b_h + SM_B_TILE;

#pragma unroll
        for (int kf = 0; kf < 2; ++kf) {
            uint32_t ah[4][4], al[4][4], bh[2][4], bl[2][4];
            const int arow = lid & 15;
            const int acol = kf * 16 + (lid >> 4) * 8;
#pragma unroll
            for (int mf = 0; mf < 4; ++mf) {
                uint32_t off = (uint32_t)((wm + mf * 16 + arow) * 80 + acol * 2);
                ldsm4(a_h + off, ah[mf]);
                ldsm4(a_l + off, al[mf]);
            }
            const int brow = kf * 16 + (lid & 15);
            const int bcol = (lid >> 4) * 8;
#pragma unroll
            for (int nf2 = 0; nf2 < 2; ++nf2) {
                uint32_t off = (uint32_t)(brow * 272 + (wn + nf2 * 16 + bcol) * 2);
                ldsm4t(b_h + off, bh[nf2]);
                ldsm4t(b_l + off, bl[nf2]);
            }
#pragma unroll
            for (int mf = 0; mf < 4; ++mf)
#pragma unroll
                for (int nf = 0; nf < 4; ++nf) {
                    const uint32_t* bhf = &bh[nf >> 1][(nf & 1) * 2];
                    const uint32_t* blf = &bl[nf >> 1][(nf & 1) * 2];
                    mma16816(acc[mf][nf], ah[mf], bhf);
                    mma16816(acc[mf][nf], ah[mf], blf);
                    mma16816(acc[mf][nf], al[mf], bhf);
                }
        }
        __syncthreads();
    }

    // epilogue: bias + direct coalesced-ish float2 stores
    float* outp = g_qkv + (size_t)b * C3 * HW;
#pragma unroll
    for (int mf = 0; mf < 4; ++mf) {
        const int r = m0 + wm + mf * 16 + (lid >> 2);
        const float bv0 = __ldg(bias + r);
        const float bv1 = __ldg(bias + r + 8);
#pragma unroll
        for (int nf = 0; nf < 4; ++nf) {
            const int cc = n0 + wn + nf * 8 + 2 * (lid & 3);
            float2 v0 = make_float2(acc[mf][nf][0] + bv0, acc[mf][nf][1] + bv0);
            float2 v1 = make_float2(acc[mf][nf][2] + bv1, acc[mf][nf][3] + bv1);
            *(float2*)(outp + (size_t)r * HW + cc) = v0;
            *(float2*)(outp + (size_t)(r + 8) * HW + cc) = v1;
        }
    }
}

// ---------------- Kernel 2: depthwise 3x3, smem-tiled ----------------
__global__ void __launch_bounds__(256) dwconv_kernel(
    const float* __restrict__ w, const float* __restrict__ bias, int mod)
{
    __shared__ float t[34][130];
    const int c = blockIdx.y, b = blockIdx.z;
    const int r0 = blockIdx.x * 32;
    const int tid = threadIdx.x;
    const float* xc = g_qkv + ((size_t)b * C3 + c) * HW;

    for (int idx = tid; idx < 34 * 128; idx += 256) {
        int rr = idx >> 7, j = idx & 127;
        int gr = r0 - 1 + rr;
        t[rr][j] = ((unsigned)gr < 128u) ? xc[gr * 128 + j] : 0.f;
    }
    float wv[9];
#pragma unroll
    for (int k = 0; k < 9; ++k) wv[k] = __ldg(w + c * 9 + k);
    const float bz = __ldg(bias + c);
    __syncthreads();

    const int j = tid & 127;
    float* op = g_dw[mod] + ((size_t)b * C3 + c) * HW + (size_t)r0 * 128 + j;
#pragma unroll
    for (int it = 0; it < 16; ++it) {
        int lr = (tid >> 7) + it * 2;
        float acc = bz;
#pragma unroll
        for (int dy = 0; dy < 3; ++dy) {
            const float* row = &t[lr + dy][0];
            if (j > 0)   acc += wv[dy * 3 + 0] * row[j - 1];
                         acc += wv[dy * 3 + 1] * row[j];
            if (j < 127) acc += wv[dy * 3 + 2] * row[j + 1];
        }
        op[(size_t)lr * 128] = acc;
    }
}

// ---------------- Kernel 3a: partial channel-attn dots + sq over n-chunk ----
__global__ void __launch_bounds__(256) attn_partial_kernel()
{
    const int h = blockIdx.x, b = blockIdx.y, chunk = blockIdx.z;
    const int t = threadIdx.x;

    __shared__ float tile[4][8][132];
    __shared__ float red[256];

    const size_t base = (size_t)b * C3 * HW + (size_t)h * CH * HW;
    const float* t_hq = g_dw[0] + base;
    const float* t_lk = g_dw[1] + base + (size_t)CDIM * HW;
    const float* t_lq = g_dw[1] + base;
    const float* t_hk = g_dw[0] + base + (size_t)CDIM * HW;

    const int pairattn = t & 127;
    const int jp   = t >> 7;
    const int attn = pairattn >> 6;
    const int c    = (pairattn >> 3) & 7;
    const int d    = pairattn & 7;

    float acc = 0.f, sq = 0.f;
    const int col = t & 127;
    const int r0  = t >> 7;

    const int nbeg = chunk * 2048;
    for (int n0 = nbeg; n0 < nbeg + 2048; n0 += 128) {
#pragma unroll
        for (int it = 0; it < 16; ++it) {
            const int tens = it >> 2;
            const int row  = (r0 + 2 * it) & 7;
            const float* src = (tens == 0) ? t_hq : (tens == 1) ? t_lk
                             : (tens == 2) ? t_lq : t_hk;
            tile[tens][row][col] = __ldg(src + (size_t)row * HW + n0 + col);
        }
        __syncthreads();

        const float* qrow = &tile[attn * 2][c][0];
        const float* krow = &tile[attn * 2 + 1][d][0];
#pragma unroll 8
        for (int jj = jp * 64; jj < jp * 64 + 64; ++jj)
            acc += qrow[jj] * krow[jj];

        if (t < 32) {
            const float* rr = &tile[t >> 3][t & 7][0];
#pragma unroll 8
            for (int jj = 0; jj < 128; ++jj) sq += rr[jj] * rr[jj];
        }
        __syncthreads();
    }

    red[t] = acc;
    __syncthreads();
    float* gp = g_part + (((size_t)chunk * BATCH + b) * HEADS + h) * 160;
    if (t < 128) gp[t] = red[t] + red[t + 128];
    if (t < 32)  gp[128 + t] = sq;
}

// ---------------- Kernel 3b: finalize attention scores ----------------
__global__ void __launch_bounds__(128) attn_final_kernel(
    const float* __restrict__ temp1, const float* __restrict__ temp2)
{
    const int h = blockIdx.x, b = blockIdx.y, t = threadIdx.x;
    __shared__ float invn[32];

    float dot = 0.f;
#pragma unroll
    for (int chv = 0; chv < 8; ++chv)
        dot += g_part[(((size_t)chv * BATCH + b) * HEADS + h) * 160 + t];
    if (t < 32) {
        float sq = 0.f;
#pragma unroll
        for (int chv = 0; chv < 8; ++chv)
            sq += g_part[(((size_t)chv * BATCH + b) * HEADS + h) * 160 + 128 + t];
        invn[t] = 1.f / fmaxf(sqrtf(sq), EPSN);
    }
    __syncthreads();
    const int attn = t >> 6, c = (t >> 3) & 7, d = t & 7;
    float tmp = attn ? __ldg(temp2 + h) : __ldg(temp1 + h);
    float scale = invn[(attn * 2) * 8 + c] * invn[(attn * 2 + 1) * 8 + d] * tmp;
    g_attn[(((size_t)attn * BATCH + b) * HEADS + h) * 64 + c * 8 + d] = dot * scale;
}

// ---------------- Kernel 4: conv fusion + BN + ReLU + softmax ----------------
__global__ void __launch_bounds__(512) fuse_kernel(
    const float* __restrict__ pw, const float* __restrict__ pb,
    const float* __restrict__ gamma, const float* __restrict__ beta,
    const float* __restrict__ mean, const float* __restrict__ var)
{
    const int b = blockIdx.x;
    const int t = threadIdx.x;
    __shared__ float a1s[HEADS * 64];
    __shared__ float a2s[HEADS * 64];

#pragma unroll
    for (int it = 0; it < 8; ++it) {
        int idx = t + it * 512;
        a1s[idx] = g_attn[(size_t)b * 4096 + idx];
        a2s[idx] = g_attn[((size_t)BATCH + b) * 4096 + idx];
    }
    __syncthreads();

    const int ho = t >> 3;
    const int c  = t & 7;
    float f[8] = {0, 0, 0, 0, 0, 0, 0, 0};
    for (int hi = 0; hi < 64; ++hi) {
        float w1 = __ldg(pw + ho * 128 + hi);
        float w2 = __ldg(pw + ho * 128 + 64 + hi);
#pragma unroll
        for (int dd = 0; dd < 8; ++dd) {
            f[dd] += w1 * a1s[hi * 64 + c * 8 + dd];
            f[dd] += w2 * a2s[hi * 64 + c * 8 + dd];
        }
    }
    const float inv_std = rsqrtf(__ldg(var + ho) + EPSBN);
    const float g = __ldg(gamma + ho), bb = __ldg(beta + ho);
    const float mu = __ldg(mean + ho), pbi = __ldg(pb + ho);
#pragma unroll
    for (int dd = 0; dd < 8; ++dd)
        f[dd] = fmaxf((f[dd] + pbi - mu) * inv_std * g + bb, 0.f);

#pragma unroll
    for (int which = 0; which < 2; ++which) {
        const float* as = which ? a2s : a1s;
        float s[8], mx = -1e30f;
#pragma unroll
        for (int dd = 0; dd < 8; ++dd) {
            s[dd] = f[dd] + as[ho * 64 + c * 8 + dd];
            mx = fmaxf(mx, s[dd]);
        }
        float sum = 0.f;
#pragma unroll
        for (int dd = 0; dd < 8; ++dd) { s[dd] = expf(s[dd] - mx); sum += s[dd]; }
        float inv = 1.f / sum;
#pragma unroll
        for (int dd = 0; dd < 8; ++dd)
            g_aw[((size_t)which * BATCH + b) * 4096 + t * 8 + dd] = s[dd] * inv;
    }
}

// ---------------- Kernel 5: output einsum + residuals ----------------
__global__ void __launch_bounds__(256) out_kernel(
    const float* __restrict__ hsi, const float* __restrict__ lidar,
    float* __restrict__ out)
{
    const int h   = blockIdx.y;
    const int zz  = blockIdx.z;
    const int mod = zz >> 1;
    const int b   = zz & 1;
    const int t   = threadIdx.x;

    __shared__ float aw[64];
    if (t < 64)
        aw[t] = g_aw[(((size_t)mod * BATCH + b) * HEADS + h) * 64 + t];
    __syncthreads();

    const float* vsrc = g_dw[mod] + ((size_t)b * C3 + 2 * CDIM + h * CH) * HW;
    const float* xin  = (mod ? lidar : hsi) + ((size_t)b * CDIM + h * CH) * HW;
    float* o = out + (size_t)mod * BATCH * CDIM * HW + ((size_t)b * CDIM + h * CH) * HW;

    const int n = blockIdx.x * 256 + t;
    float v[8];
#pragma unroll
    for (int dd = 0; dd < 8; ++dd) v[dd] = __ldg(vsrc + (size_t)dd * HW + n);

#pragma unroll
    for (int c = 0; c < 8; ++c) {
        float s = __ldg(xin + (size_t)c * HW + n) + v[c];
#pragma unroll
        for (int dd = 0; dd < 8; ++dd) s += aw[c * 8 + dd] * v[dd];
        o[(size_t)c * HW + n] = s;
    }
}

// ---------------- launch ----------------
extern "C" void kernel_launch(void* const* d_in, const int* in_sizes, int n_in,
                              void* d_out, int out_size)
{
    const float* hsi        = (const float*)d_in[0];
    const float* lidar      = (const float*)d_in[1];
    const float* hsi_qkv_w  = (const float*)d_in[2];
    const float* hsi_qkv_b  = (const float*)d_in[3];
    const float* lidar_qkv_w= (const float*)d_in[4];
    const float* lidar_qkv_b= (const float*)d_in[5];
    const float* hsi_dw_w   = (const float*)d_in[6];
    const float* hsi_dw_b   = (const float*)d_in[7];
    const float* lidar_dw_w = (const float*)d_in[8];
    const float* lidar_dw_b = (const float*)d_in[9];
    const float* temp1      = (const float*)d_in[10];
    const float* temp2      = (const float*)d_in[11];
    const float* proj_w     = (const float*)d_in[12];
    const float* proj_b     = (const float*)d_in[13];
    const float* bn_gamma   = (const float*)d_in[14];
    const float* bn_beta    = (const float*)d_in[15];
    const float* bn_mean    = (const float*)d_in[16];
    const float* bn_var     = (const float*)d_in[17];
    float* out = (float*)d_out;

    static int smem_set = 0;
    if (!smem_set) {
        cudaFuncSetAttribute(qkv_gemm_mma,
                             cudaFuncAttributeMaxDynamicSharedMemorySize, GEMM_SMEM);
        smem_set = 1;
    }

    __nv_bfloat16 *wh, *wl, *xh, *xl;
    cudaGetSymbolAddress((void**)&wh, g_wh);
    cudaGetSymbolAddress((void**)&wl, g_wl);
    cudaGetSymbolAddress((void**)&xh, g_xh);
    cudaGetSymbolAddress((void**)&xl, g_xl);

    const int w4 = C3 * CDIM / 4;                 // 196608
    const int x4 = BATCH * CDIM * HW / 4;         // 4194304

    dim3 ggrid(HW / 128, C3 / 128, BATCH);        // 128 x 12 x 2
    dim3 dgrid(4, C3, BATCH);

    // modality 0 (hsi)
    cvt_split_kernel<<<(w4 + 255) / 256, 256>>>(hsi_qkv_w, wh, wl, w4);
    cvt_split_kernel<<<(x4 + 255) / 256, 256>>>(hsi, xh, xl, x4);
    qkv_gemm_mma<<<ggrid, 256, GEMM_SMEM>>>(hsi_qkv_b);
    dwconv_kernel<<<dgrid, 256>>>(hsi_dw_w, hsi_dw_b, 0);

    // modality 1 (lidar)
    cvt_split_kernel<<<(w4 + 255) / 256, 256>>>(lidar_qkv_w, wh, wl, w4);
    cvt_split_kernel<<<(x4 + 255) / 256, 256>>>(lidar, xh, xl, x4);
    qkv_gemm_mma<<<ggrid, 256, GEMM_SMEM>>>(lidar_qkv_b);
    dwconv_kernel<<<dgrid, 256>>>(lidar_dw_w, lidar_dw_b, 1);

    attn_partial_kernel<<<dim3(HEADS, BATCH, 8), 256>>>();
    attn_final_kernel<<<dim3(HEADS, BATCH), 128>>>(temp1, temp2);
    fuse_kernel<<<BATCH, 512>>>(proj_w, proj_b, bn_gamma, bn_beta, bn_mean, bn_var);
    out_kernel<<<dim3(HW / 256, HEADS, BATCH * 2), 256>>>(hsi, lidar, out);
}

// round 5
// speedup vs baseline: 3.2015x; 1.2623x over previous
#include <cuda_runtime.h>
#include <cuda_fp16.h>
#include <cstdint>
#include <math.h>

// ---------------- problem constants ----------------
#define BATCH   2
#define CDIM    512
#define C3      1536
#define HW      16384
#define HEADS   64
#define CH      8
#define EPSN    1e-12f
#define EPSBN   1e-5f

// ---------------- scratch ----------------
__device__ float g_qkv[BATCH * C3 * HW];                 // qkv conv out (per modality)
__device__ float g_dw[2][BATCH * C3 * HW];               // post-dwconv q/k/v
__device__ float g_part[8 * BATCH * HEADS * 160];        // partial dots(128)+sq(32)
__device__ float g_attn[2 * BATCH * HEADS * CH * CH];
__device__ float g_aw[2 * BATCH * HEADS * CH * CH];
__device__ __half g_wf[C3 * CDIM];                       // w single fp16
__device__ __half g_xh[BATCH * CDIM * HW], g_xl[BATCH * CDIM * HW];  // x hi/lo fp16

// ---------------- PTX helpers (sm_80-era, valid on plain sm_103 target) -----
__device__ __forceinline__ uint32_t smem_u32(const void* p) {
    uint32_t a;
    asm("{ .reg .u64 t; cvta.to.shared.u64 t, %1; cvt.u32.u64 %0, t; }" : "=r"(a) : "l"(p));
    return a;
}
__device__ __forceinline__ void cpasync16(uint32_t saddr, const void* g) {
    asm volatile("cp.async.cg.shared.global [%0], [%1], 16;" :: "r"(saddr), "l"(g));
}
__device__ __forceinline__ void ldsm4(uint32_t addr, uint32_t* r) {
    asm volatile("ldmatrix.sync.aligned.m8n8.x4.shared.b16 {%0,%1,%2,%3}, [%4];"
        : "=r"(r[0]), "=r"(r[1]), "=r"(r[2]), "=r"(r[3]) : "r"(addr));
}
__device__ __forceinline__ void ldsm4t(uint32_t addr, uint32_t* r) {
    asm volatile("ldmatrix.sync.aligned.m8n8.x4.trans.shared.b16 {%0,%1,%2,%3}, [%4];"
        : "=r"(r[0]), "=r"(r[1]), "=r"(r[2]), "=r"(r[3]) : "r"(addr));
}
__device__ __forceinline__ void mma16816(float* c, const uint32_t* a, const uint32_t* b) {
    asm volatile("mma.sync.aligned.m16n8k16.row.col.f32.f16.f16.f32 "
        "{%0,%1,%2,%3}, {%4,%5,%6,%7}, {%8,%9}, {%0,%1,%2,%3};"
        : "+f"(c[0]), "+f"(c[1]), "+f"(c[2]), "+f"(c[3])
        : "r"(a[0]), "r"(a[1]), "r"(a[2]), "r"(a[3]), "r"(b[0]), "r"(b[1]));
}

// ---------------- Kernel 0a: x fp32 -> fp16 hi/lo split ----------------
__global__ void __launch_bounds__(256) cvt_split_x(
    const float* __restrict__ src, __half* __restrict__ dh,
    __half* __restrict__ dl, int n4)
{
    int i = blockIdx.x * 256 + threadIdx.x;
    if (i >= n4) return;
    float4 v = ((const float4*)src)[i];
    float vv[4] = {v.x, v.y, v.z, v.w};
    __half h[4], l[4];
#pragma unroll
    for (int j = 0; j < 4; ++j) {
        h[j] = __float2half_rn(vv[j]);
        l[j] = __float2half_rn(vv[j] - __half2float(h[j]));
    }
    ((uint2*)dh)[i] = *(uint2*)h;
    ((uint2*)dl)[i] = *(uint2*)l;
}

// ---------------- Kernel 0b: w fp32 -> fp16 single ----------------
__global__ void __launch_bounds__(256) cvt_w(
    const float* __restrict__ src, __half* __restrict__ dh, int n4)
{
    int i = blockIdx.x * 256 + threadIdx.x;
    if (i >= n4) return;
    float4 v = ((const float4*)src)[i];
    __half h[4] = { __float2half_rn(v.x), __float2half_rn(v.y),
                    __float2half_rn(v.z), __float2half_rn(v.w) };
    ((uint2*)dh)[i] = *(uint2*)h;
}

// ---------------- Kernel 1: qkv GEMM via mma.sync fp16 2-product ----------
// y[b][m][n] = bias[m] + sum_k w[m][k] x[b][k][n];  w single fp16, x hi/lo.
// CTA 128(M) x 128(N), BK=32, double-buffered cp.async, 8 warps (2m x 4n).
#define SM_A_STAGE 10240          // 128 rows * 80B (64B data + pad)
#define SM_B_BASE  20480
#define SM_B_STAGE 17408          // (Bh+Bl), 32 rows * 272B each
#define SM_B_TILE  8704
#define GEMM_SMEM  55296

__device__ __forceinline__ void gemm_load_stage(
    uint32_t sb, int s, int k0, const __half* wp,
    const __half* xph, const __half* xpl, int tid)
{
    uint32_t a_h = sb + s * SM_A_STAGE;
    uint32_t b_h = sb + SM_B_BASE + s * SM_B_STAGE, b_l = b_h + SM_B_TILE;
#pragma unroll
    for (int it = 0; it < 2; ++it) {
        int cid = tid + it * 256;
        int r = cid >> 2, c = cid & 3;
        cpasync16(a_h + r * 80 + c * 16, wp + (size_t)r * CDIM + k0 + c * 8);
    }
#pragma unroll
    for (int it = 0; it < 2; ++it) {
        int cid = tid + it * 256;
        int r = cid >> 4, c = cid & 15;
        uint32_t soff = r * 272 + c * 16;
        cpasync16(b_h + soff, xph + (size_t)(k0 + r) * HW + c * 8);
        cpasync16(b_l + soff, xpl + (size_t)(k0 + r) * HW + c * 8);
    }
    asm volatile("cp.async.commit_group;");
}

__global__ void __launch_bounds__(256, 1) qkv_gemm_mma(
    const float* __restrict__ bias)
{
    extern __shared__ char smem[];
    const uint32_t sb = smem_u32(smem);
    const int tid = threadIdx.x;
    const int warp = tid >> 5, lid = tid & 31;
    const int n0 = blockIdx.x * 128;
    const int m0 = blockIdx.y * 128;
    const int b  = blockIdx.z;

    const __half* wp  = g_wf + (size_t)m0 * CDIM;
    const __half* xph = g_xh + (size_t)b * CDIM * HW + n0;
    const __half* xpl = g_xl + (size_t)b * CDIM * HW + n0;

    float acc[4][4][4];
#pragma unroll
    for (int i = 0; i < 4; ++i)
#pragma unroll
        for (int j = 0; j < 4; ++j)
#pragma unroll
            for (int q = 0; q < 4; ++q) acc[i][j][q] = 0.f;

    const int wm = (warp & 1) * 64;
    const int wn = (warp >> 1) * 32;

    gemm_load_stage(sb, 0, 0, wp, xph, xpl, tid);

    for (int ks = 0; ks < 16; ++ks) {
        const int s = ks & 1;
        if (ks + 1 < 16) {
            gemm_load_stage(sb, s ^ 1, (ks + 1) * 32, wp, xph, xpl, tid);
            asm volatile("cp.async.wait_group 1;");
        } else {
            asm volatile("cp.async.wait_group 0;");
        }
        __syncthreads();

        uint32_t a_h = sb + s * SM_A_STAGE;
        uint32_t b_h = sb + SM_B_BASE + s * SM_B_STAGE, b_l = b_h + SM_B_TILE;

#pragma unroll
        for (int kf = 0; kf < 2; ++kf) {
            uint32_t ah[4][4], bh[2][4], bl[2][4];
            const int arow = lid & 15;
            const int acol = kf * 16 + (lid >> 4) * 8;
#pragma unroll
            for (int mf = 0; mf < 4; ++mf) {
                uint32_t off = (uint32_t)((wm + mf * 16 + arow) * 80 + acol * 2);
                ldsm4(a_h + off, ah[mf]);
            }
            const int brow = kf * 16 + (lid & 15);
            const int bcol = (lid >> 4) * 8;
#pragma unroll
            for (int nf2 = 0; nf2 < 2; ++nf2) {
                uint32_t off = (uint32_t)(brow * 272 + (wn + nf2 * 16 + bcol) * 2);
                ldsm4t(b_h + off, bh[nf2]);
                ldsm4t(b_l + off, bl[nf2]);
            }
#pragma unroll
            for (int mf = 0; mf < 4; ++mf)
#pragma unroll
                for (int nf = 0; nf < 4; ++nf) {
                    const uint32_t* bhf = &bh[nf >> 1][(nf & 1) * 2];
                    const uint32_t* blf = &bl[nf >> 1][(nf & 1) * 2];
                    mma16816(acc[mf][nf], ah[mf], bhf);
                    mma16816(acc[mf][nf], ah[mf], blf);
                }
        }
        __syncthreads();
    }

    float* outp = g_qkv + (size_t)b * C3 * HW;
#pragma unroll
    for (int mf = 0; mf < 4; ++mf) {
        const int r = m0 + wm + mf * 16 + (lid >> 2);
        const float bv0 = __ldg(bias + r);
        const float bv1 = __ldg(bias + r + 8);
#pragma unroll
        for (int nf = 0; nf < 4; ++nf) {
            const int cc = n0 + wn + nf * 8 + 2 * (lid & 3);
            float2 v0 = make_float2(acc[mf][nf][0] + bv0, acc[mf][nf][1] + bv0);
            float2 v1 = make_float2(acc[mf][nf][2] + bv1, acc[mf][nf][3] + bv1);
            *(float2*)(outp + (size_t)r * HW + cc) = v0;
            *(float2*)(outp + (size_t)(r + 8) * HW + cc) = v1;
        }
    }
}

// ---------------- Kernel 2: depthwise 3x3, sliding-window ----------------
// tile cols shifted by 1; col 0 and 129 are zero guards -> no predicates.
__global__ void __launch_bounds__(256) dwconv_kernel(
    const float* __restrict__ w, const float* __restrict__ bias, int mod)
{
    __shared__ float t[34][132];
    const int c = blockIdx.y, b = blockIdx.z;
    const int r0 = blockIdx.x * 32;
    const int tid = threadIdx.x;
    const float* xc = g_qkv + ((size_t)b * C3 + c) * HW;

    for (int idx = tid; idx < 34 * 128; idx += 256) {
        int rr = idx >> 7, j = idx & 127;
        int gr = r0 - 1 + rr;
        t[rr][j + 1] = ((unsigned)gr < 128u) ? xc[gr * 128 + j] : 0.f;
    }
    if (tid < 34) { t[tid][0] = 0.f; t[tid][129] = 0.f; }

    float wv[9];
#pragma unroll
    for (int k = 0; k < 9; ++k) wv[k] = __ldg(w + c * 9 + k);
    const float bz = __ldg(bias + c);
    __syncthreads();

    const int j = tid & 127;
    const int base = (tid >> 7) * 16;       // 0 or 16: output-row group
    float* op = g_dw[mod] + ((size_t)b * C3 + c) * HW + (size_t)(r0 + base) * 128 + j;

    float a0 = t[base][j],     a1 = t[base][j + 1],     a2 = t[base][j + 2];
    float b0 = t[base + 1][j], b1 = t[base + 1][j + 1], b2 = t[base + 1][j + 2];
#pragma unroll
    for (int s = 0; s < 16; ++s) {
        const float* nr = &t[base + 2 + s][0];
        float n0 = nr[j], n1 = nr[j + 1], n2 = nr[j + 2];
        float acc = bz;
        acc += wv[0] * a0 + wv[1] * a1 + wv[2] * a2;
        acc += wv[3] * b0 + wv[4] * b1 + wv[5] * b2;
        acc += wv[6] * n0 + wv[7] * n1 + wv[8] * n2;
        op[(size_t)s * 128] = acc;
        a0 = b0; a1 = b1; a2 = b2;
        b0 = n0; b1 = n1; b2 = n2;
    }
}

// ---------------- Kernel 3a: partial channel-attn dots + sq over n-chunk ----
__global__ void __launch_bounds__(256) attn_partial_kernel()
{
    const int h = blockIdx.x, b = blockIdx.y, chunk = blockIdx.z;
    const int t = threadIdx.x;

    __shared__ float tile[4][8][132];
    __shared__ float red[256];

    const size_t base = (size_t)b * C3 * HW + (size_t)h * CH * HW;
    const float* t_hq = g_dw[0] + base;
    const float* t_lk = g_dw[1] + base + (size_t)CDIM * HW;
    const float* t_lq = g_dw[1] + base;
    const float* t_hk = g_dw[0] + base + (size_t)CDIM * HW;

    const int pairattn = t & 127;
    const int jp   = t >> 7;
    const int attn = pairattn >> 6;
    const int c    = (pairattn >> 3) & 7;
    const int d    = pairattn & 7;

    float acc = 0.f, sq = 0.f;
    const int col = t & 127;
    const int r0  = t >> 7;

    const int nbeg = chunk * 2048;
    for (int n0 = nbeg; n0 < nbeg + 2048; n0 += 128) {
#pragma unroll
        for (int it = 0; it < 16; ++it) {
            const int tens = it >> 2;
            const int row  = (r0 + 2 * it) & 7;
            const float* src = (tens == 0) ? t_hq : (tens == 1) ? t_lk
                             : (tens == 2) ? t_lq : t_hk;
            tile[tens][row][col] = __ldg(src + (size_t)row * HW + n0 + col);
        }
        __syncthreads();

        const float* qrow = &tile[attn * 2][c][0];
        const float* krow = &tile[attn * 2 + 1][d][0];
#pragma unroll 8
        for (int jj = jp * 64; jj < jp * 64 + 64; ++jj)
            acc += qrow[jj] * krow[jj];

        if (t < 32) {
            const float* rr = &tile[t >> 3][t & 7][0];
#pragma unroll 8
            for (int jj = 0; jj < 128; ++jj) sq += rr[jj] * rr[jj];
        }
        __syncthreads();
    }

    red[t] = acc;
    __syncthreads();
    float* gp = g_part + (((size_t)chunk * BATCH + b) * HEADS + h) * 160;
    if (t < 128) gp[t] = red[t] + red[t + 128];
    if (t < 32)  gp[128 + t] = sq;
}

// ---------------- Kernel 3b: finalize attention scores ----------------
__global__ void __launch_bounds__(128) attn_final_kernel(
    const float* __restrict__ temp1, const float* __restrict__ temp2)
{
    const int h = blockIdx.x, b = blockIdx.y, t = threadIdx.x;
    __shared__ float invn[32];

    float dot = 0.f;
#pragma unroll
    for (int chv = 0; chv < 8; ++chv)
        dot += g_part[(((size_t)chv * BATCH + b) * HEADS + h) * 160 + t];
    if (t < 32) {
        float sq = 0.f;
#pragma unroll
        for (int chv = 0; chv < 8; ++chv)
            sq += g_part[(((size_t)chv * BATCH + b) * HEADS + h) * 160 + 128 + t];
        invn[t] = 1.f / fmaxf(sqrtf(sq), EPSN);
    }
    __syncthreads();
    const int attn = t >> 6, c = (t >> 3) & 7, d = t & 7;
    float tmp = attn ? __ldg(temp2 + h) : __ldg(temp1 + h);
    float scale = invn[(attn * 2) * 8 + c] * invn[(attn * 2 + 1) * 8 + d] * tmp;
    g_attn[(((size_t)attn * BATCH + b) * HEADS + h) * 64 + c * 8 + d] = dot * scale;
}

// ---------------- Kernel 4: conv fusion + BN + ReLU + softmax ----------------
__global__ void __launch_bounds__(512) fuse_kernel(
    const float* __restrict__ pw, const float* __restrict__ pb,
    const float* __restrict__ gamma, const float* __restrict__ beta,
    const float* __restrict__ mean, const float* __restrict__ var)
{
    const int b = blockIdx.x;
    const int t = threadIdx.x;
    __shared__ float a1s[HEADS * 64];
    __shared__ float a2s[HEADS * 64];

#pragma unroll
    for (int it = 0; it < 8; ++it) {
        int idx = t + it * 512;
        a1s[idx] = g_attn[(size_t)b * 4096 + idx];
        a2s[idx] = g_attn[((size_t)BATCH + b) * 4096 + idx];
    }
    __syncthreads();

    const int ho = t >> 3;
    const int c  = t & 7;
    float f[8] = {0, 0, 0, 0, 0, 0, 0, 0};
    for (int hi = 0; hi < 64; ++hi) {
        float w1 = __ldg(pw + ho * 128 + hi);
        float w2 = __ldg(pw + ho * 128 + 64 + hi);
#pragma unroll
        for (int dd = 0; dd < 8; ++dd) {
            f[dd] += w1 * a1s[hi * 64 + c * 8 + dd];
            f[dd] += w2 * a2s[hi * 64 + c * 8 + dd];
        }
    }
    const float inv_std = rsqrtf(__ldg(var + ho) + EPSBN);
    const float g = __ldg(gamma + ho), bb = __ldg(beta + ho);
    const float mu = __ldg(mean + ho), pbi = __ldg(pb + ho);
#pragma unroll
    for (int dd = 0; dd < 8; ++dd)
        f[dd] = fmaxf((f[dd] + pbi - mu) * inv_std * g + bb, 0.f);

#pragma unroll
    for (int which = 0; which < 2; ++which) {
        const float* as = which ? a2s : a1s;
        float s[8], mx = -1e30f;
#pragma unroll
        for (int dd = 0; dd < 8; ++dd) {
            s[dd] = f[dd] + as[ho * 64 + c * 8 + dd];
            mx = fmaxf(mx, s[dd]);
        }
        float sum = 0.f;
#pragma unroll
        for (int dd = 0; dd < 8; ++dd) { s[dd] = expf(s[dd] - mx); sum += s[dd]; }
        float inv = 1.f / sum;
#pragma unroll
        for (int dd = 0; dd < 8; ++dd)
            g_aw[((size_t)which * BATCH + b) * 4096 + t * 8 + dd] = s[dd] * inv;
    }
}

// ---------------- Kernel 5: output einsum + residuals (float4) -------------
__global__ void __launch_bounds__(256) out_kernel(
    const float* __restrict__ hsi, const float* __restrict__ lidar,
    float* __restrict__ out)
{
    const int h   = blockIdx.y;
    const int zz  = blockIdx.z;
    const int mod = zz >> 1;
    const int b   = zz & 1;
    const int t   = threadIdx.x;

    __shared__ float aw[64];
    if (t < 64)
        aw[t] = g_aw[(((size_t)mod * BATCH + b) * HEADS + h) * 64 + t];
    __syncthreads();

    const float* vsrc = g_dw[mod] + ((size_t)b * C3 + 2 * CDIM + h * CH) * HW;
    const float* xin  = (mod ? lidar : hsi) + ((size_t)b * CDIM + h * CH) * HW;
    float* o = out + (size_t)mod * BATCH * CDIM * HW + ((size_t)b * CDIM + h * CH) * HW;

    const int n = (blockIdx.x * 256 + t) * 4;
    float4 v[8];
#pragma unroll
    for (int dd = 0; dd < 8; ++dd) v[dd] = *(const float4*)(vsrc + (size_t)dd * HW + n);

#pragma unroll
    for (int c = 0; c < 8; ++c) {
        float4 s = *(const float4*)(xin + (size_t)c * HW + n);
        s.x += v[c].x; s.y += v[c].y; s.z += v[c].z; s.w += v[c].w;
#pragma unroll
        for (int dd = 0; dd < 8; ++dd) {
            const float a = aw[c * 8 + dd];
            s.x += a * v[dd].x; s.y += a * v[dd].y;
            s.z += a * v[dd].z; s.w += a * v[dd].w;
        }
        *(float4*)(o + (size_t)c * HW + n) = s;
    }
}

// ---------------- launch ----------------
extern "C" void kernel_launch(void* const* d_in, const int* in_sizes, int n_in,
                              void* d_out, int out_size)
{
    const float* hsi        = (const float*)d_in[0];
    const float* lidar      = (const float*)d_in[1];
    const float* hsi_qkv_w  = (const float*)d_in[2];
    const float* hsi_qkv_b  = (const float*)d_in[3];
    const float* lidar_qkv_w= (const float*)d_in[4];
    const float* lidar_qkv_b= (const float*)d_in[5];
    const float* hsi_dw_w   = (const float*)d_in[6];
    const float* hsi_dw_b   = (const float*)d_in[7];
    const float* lidar_dw_w = (const float*)d_in[8];
    const float* lidar_dw_b = (const float*)d_in[9];
    const float* temp1      = (const float*)d_in[10];
    const float* temp2      = (const float*)d_in[11];
    const float* proj_w     = (const float*)d_in[12];
    const float* proj_b     = (const float*)d_in[13];
    const float* bn_gamma   = (const float*)d_in[14];
    const float* bn_beta    = (const float*)d_in[15];
    const float* bn_mean    = (const float*)d_in[16];
    const float* bn_var     = (const float*)d_in[17];
    float* out = (float*)d_out;

    static int smem_set = 0;
    if (!smem_set) {
        cudaFuncSetAttribute(qkv_gemm_mma,
                             cudaFuncAttributeMaxDynamicSharedMemorySize, GEMM_SMEM);
        smem_set = 1;
    }

    __half *wf, *xh, *xl;
    cudaGetSymbolAddress((void**)&wf, g_wf);
    cudaGetSymbolAddress((void**)&xh, g_xh);
    cudaGetSymbolAddress((void**)&xl, g_xl);

    const int w4 = C3 * CDIM / 4;
    const int x4 = BATCH * CDIM * HW / 4;

    dim3 ggrid(HW / 128, C3 / 128, BATCH);
    dim3 dgrid(4, C3, BATCH);

    // modality 0 (hsi)
    cvt_w<<<(w4 + 255) / 256, 256>>>(hsi_qkv_w, wf, w4);
    cvt_split_x<<<(x4 + 255) / 256, 256>>>(hsi, xh, xl, x4);
    qkv_gemm_mma<<<ggrid, 256, GEMM_SMEM>>>(hsi_qkv_b);
    dwconv_kernel<<<dgrid, 256>>>(hsi_dw_w, hsi_dw_b, 0);

    // modality 1 (lidar)
    cvt_w<<<(w4 + 255) / 256, 256>>>(lidar_qkv_w, wf, w4);
    cvt_split_x<<<(x4 + 255) / 256, 256>>>(lidar, xh, xl, x4);
    qkv_gemm_mma<<<ggrid, 256, GEMM_SMEM>>>(lidar_qkv_b);
    dwconv_kernel<<<dgrid, 256>>>(lidar_dw_w, lidar_dw_b, 1);

    attn_partial_kernel<<<dim3(HEADS, BATCH, 8), 256>>>();
    attn_final_kernel<<<dim3(HEADS, BATCH), 128>>>(temp1, temp2);
    fuse_kernel<<<BATCH, 512>>>(proj_w, proj_b, bn_gamma, bn_beta, bn_mean, bn_var);
    out_kernel<<<dim3(HW / 1024, HEADS, BATCH * 2), 256>>>(hsi, lidar, out);
}

// round 7
// speedup vs baseline: 3.5013x; 1.0936x over previous
#include <cuda_runtime.h>
#include <cuda_fp16.h>
#include <cstdint>
#include <math.h>

// ---------------- problem constants ----------------
#define BATCH   2
#define CDIM    512
#define C3      1536
#define HW      16384
#define HEADS   64
#define CH      8
#define EPSN    1e-12f
#define EPSBN   1e-5f

// ---------------- scratch ----------------
__device__ __half g_qkv[BATCH * C3 * HW];                // qkv conv out (fp16)
__device__ __half g_dw[2][BATCH * C3 * HW];              // post-dwconv q/k/v (fp16)
__device__ float g_part[8 * BATCH * HEADS * 160];        // partial dots(128)+sq(32)
__device__ float g_attn[2 * BATCH * HEADS * CH * CH];
__device__ float g_aw[2 * BATCH * HEADS * CH * CH];
__device__ __half g_wf[C3 * CDIM];                       // w single fp16
__device__ __half g_xh[BATCH * CDIM * HW], g_xl[BATCH * CDIM * HW];  // x hi/lo fp16

// ---------------- PTX helpers (sm_80-era, valid on plain sm_103 target) -----
__device__ __forceinline__ uint32_t smem_u32(const void* p) {
    uint32_t a;
    asm("{ .reg .u64 t; cvta.to.shared.u64 t, %1; cvt.u32.u64 %0, t; }" : "=r"(a) : "l"(p));
    return a;
}
__device__ __forceinline__ void cpasync16(uint32_t saddr, const void* g) {
    asm volatile("cp.async.cg.shared.global [%0], [%1], 16;" :: "r"(saddr), "l"(g));
}
__device__ __forceinline__ void ldsm4(uint32_t addr, uint32_t* r) {
    asm volatile("ldmatrix.sync.aligned.m8n8.x4.shared.b16 {%0,%1,%2,%3}, [%4];"
        : "=r"(r[0]), "=r"(r[1]), "=r"(r[2]), "=r"(r[3]) : "r"(addr));
}
__device__ __forceinline__ void ldsm4t(uint32_t addr, uint32_t* r) {
    asm volatile("ldmatrix.sync.aligned.m8n8.x4.trans.shared.b16 {%0,%1,%2,%3}, [%4];"
        : "=r"(r[0]), "=r"(r[1]), "=r"(r[2]), "=r"(r[3]) : "r"(addr));
}
__device__ __forceinline__ void mma16816(float* c, const uint32_t* a, const uint32_t* b) {
    asm volatile("mma.sync.aligned.m16n8k16.row.col.f32.f16.f16.f32 "
        "{%0,%1,%2,%3}, {%4,%5,%6,%7}, {%8,%9}, {%0,%1,%2,%3};"
        : "+f"(c[0]), "+f"(c[1]), "+f"(c[2]), "+f"(c[3])
        : "r"(a[0]), "r"(a[1]), "r"(a[2]), "r"(a[3]), "r"(b[0]), "r"(b[1]));
}

// ---------------- Kernel 0a: x fp32 -> fp16 hi/lo split ----------------
__global__ void __launch_bounds__(256) cvt_split_x(
    const float* __restrict__ src, __half* __restrict__ dh,
    __half* __restrict__ dl, int n4)
{
    int i = blockIdx.x * 256 + threadIdx.x;
    if (i >= n4) return;
    float4 v = ((const float4*)src)[i];
    float vv[4] = {v.x, v.y, v.z, v.w};
    __half h[4], l[4];
#pragma unroll
    for (int j = 0; j < 4; ++j) {
        h[j] = __float2half_rn(vv[j]);
        l[j] = __float2half_rn(vv[j] - __half2float(h[j]));
    }
    ((uint2*)dh)[i] = *(uint2*)h;
    ((uint2*)dl)[i] = *(uint2*)l;
}

// ---------------- Kernel 0b: w fp32 -> fp16 single ----------------
__global__ void __launch_bounds__(256) cvt_w(
    const float* __restrict__ src, __half* __restrict__ dh, int n4)
{
    int i = blockIdx.x * 256 + threadIdx.x;
    if (i >= n4) return;
    float4 v = ((const float4*)src)[i];
    __half h[4] = { __float2half_rn(v.x), __float2half_rn(v.y),
                    __float2half_rn(v.z), __float2half_rn(v.w) };
    ((uint2*)dh)[i] = *(uint2*)h;
}

// ---------------- Kernel 1: qkv GEMM via mma.sync fp16 2-product ----------
#define SM_A_STAGE 10240          // 128 rows * 80B (64B data + pad)
#define SM_B_BASE  20480
#define SM_B_STAGE 17408          // (Bh+Bl), 32 rows * 272B each
#define SM_B_TILE  8704
#define GEMM_SMEM  55296

__device__ __forceinline__ void gemm_load_stage(
    uint32_t sb, int s, int k0, const __half* wp,
    const __half* xph, const __half* xpl, int tid)
{
    uint32_t a_h = sb + s * SM_A_STAGE;
    uint32_t b_h = sb + SM_B_BASE + s * SM_B_STAGE, b_l = b_h + SM_B_TILE;
#pragma unroll
    for (int it = 0; it < 2; ++it) {
        int cid = tid + it * 256;
        int r = cid >> 2, c = cid & 3;
        cpasync16(a_h + r * 80 + c * 16, wp + (size_t)r * CDIM + k0 + c * 8);
    }
#pragma unroll
    for (int it = 0; it < 2; ++it) {
        int cid = tid + it * 256;
        int r = cid >> 4, c = cid & 15;
        uint32_t soff = r * 272 + c * 16;
        cpasync16(b_h + soff, xph + (size_t)(k0 + r) * HW + c * 8);
        cpasync16(b_l + soff, xpl + (size_t)(k0 + r) * HW + c * 8);
    }
    asm volatile("cp.async.commit_group;");
}

__global__ void __launch_bounds__(256, 1) qkv_gemm_mma(
    const float* __restrict__ bias)
{
    extern __shared__ char smem[];
    const uint32_t sb = smem_u32(smem);
    const int tid = threadIdx.x;
    const int warp = tid >> 5, lid = tid & 31;
    const int n0 = blockIdx.x * 128;
    const int m0 = blockIdx.y * 128;
    const int b  = blockIdx.z;

    const __half* wp  = g_wf + (size_t)m0 * CDIM;
    const __half* xph = g_xh + (size_t)b * CDIM * HW + n0;
    const __half* xpl = g_xl + (size_t)b * CDIM * HW + n0;

    float acc[4][4][4];
#pragma unroll
    for (int i = 0; i < 4; ++i)
#pragma unroll
        for (int j = 0; j < 4; ++j)
#pragma unroll
            for (int q = 0; q < 4; ++q) acc[i][j][q] = 0.f;

    const int wm = (warp & 1) * 64;
    const int wn = (warp >> 1) * 32;

    gemm_load_stage(sb, 0, 0, wp, xph, xpl, tid);

    for (int ks = 0; ks < 16; ++ks) {
        const int s = ks & 1;
        if (ks + 1 < 16) {
            gemm_load_stage(sb, s ^ 1, (ks + 1) * 32, wp, xph, xpl, tid);
            asm volatile("cp.async.wait_group 1;");
        } else {
            asm volatile("cp.async.wait_group 0;");
        }
        __syncthreads();

        uint32_t a_h = sb + s * SM_A_STAGE;
        uint32_t b_h = sb + SM_B_BASE + s * SM_B_STAGE, b_l = b_h + SM_B_TILE;

#pragma unroll
        for (int kf = 0; kf < 2; ++kf) {
            uint32_t ah[4][4], bh[2][4], bl[2][4];
            const int arow = lid & 15;
            const int acol = kf * 16 + (lid >> 4) * 8;
#pragma unroll
            for (int mf = 0; mf < 4; ++mf) {
                uint32_t off = (uint32_t)((wm + mf * 16 + arow) * 80 + acol * 2);
                ldsm4(a_h + off, ah[mf]);
            }
            const int brow = kf * 16 + (lid & 15);
            const int bcol = (lid >> 4) * 8;
#pragma unroll
            for (int nf2 = 0; nf2 < 2; ++nf2) {
                uint32_t off = (uint32_t)(brow * 272 + (wn + nf2 * 16 + bcol) * 2);
                ldsm4t(b_h + off, bh[nf2]);
                ldsm4t(b_l + off, bl[nf2]);
            }
#pragma unroll
            for (int mf = 0; mf < 4; ++mf)
#pragma unroll
                for (int nf = 0; nf < 4; ++nf) {
                    const uint32_t* bhf = &bh[nf >> 1][(nf & 1) * 2];
                    const uint32_t* blf = &bl[nf >> 1][(nf & 1) * 2];
                    mma16816(acc[mf][nf], ah[mf], bhf);
                    mma16816(acc[mf][nf], ah[mf], blf);
                }
        }
        __syncthreads();
    }

    // epilogue: bias + fp16 stores
    __half* outp = g_qkv + (size_t)b * C3 * HW;
#pragma unroll
    for (int mf = 0; mf < 4; ++mf) {
        const int r = m0 + wm + mf * 16 + (lid >> 2);
        const float bv0 = __ldg(bias + r);
        const float bv1 = __ldg(bias + r + 8);
#pragma unroll
        for (int nf = 0; nf < 4; ++nf) {
            const int cc = n0 + wn + nf * 8 + 2 * (lid & 3);
            __half2 v0 = __floats2half2_rn(acc[mf][nf][0] + bv0, acc[mf][nf][1] + bv0);
            __half2 v1 = __floats2half2_rn(acc[mf][nf][2] + bv1, acc[mf][nf][3] + bv1);
            *(__half2*)(outp + (size_t)r * HW + cc) = v0;
            *(__half2*)(outp + (size_t)(r + 8) * HW + cc) = v1;
        }
    }
}

// ---------------- Kernel 2: depthwise 3x3, sliding-window, fp16 I/O --------
__global__ void __launch_bounds__(256) dwconv_kernel(
    const float* __restrict__ w, const float* __restrict__ bias, int mod)
{
    __shared__ float t[34][132];
    const int c = blockIdx.y, b = blockIdx.z;
    const int r0 = blockIdx.x * 32;
    const int tid = threadIdx.x;
    const __half* xc = g_qkv + ((size_t)b * C3 + c) * HW;

    for (int idx = tid; idx < 34 * 64; idx += 256) {
        int rr = idx >> 6, jp = idx & 63;
        int gr = r0 - 1 + rr;
        float2 f = make_float2(0.f, 0.f);
        if ((unsigned)gr < 128u)
            f = __half22float2(*(const __half2*)(xc + gr * 128 + jp * 2));
        t[rr][jp * 2 + 1] = f.x;
        t[rr][jp * 2 + 2] = f.y;
    }
    if (tid < 34) { t[tid][0] = 0.f; t[tid][129] = 0.f; }

    float wv[9];
#pragma unroll
    for (int k = 0; k < 9; ++k) wv[k] = __ldg(w + c * 9 + k);
    const float bz = __ldg(bias + c);
    __syncthreads();

    const int j = tid & 127;
    const int base = (tid >> 7) * 16;       // 0 or 16: output-row group
    __half* op = g_dw[mod] + ((size_t)b * C3 + c) * HW + (size_t)(r0 + base) * 128 + j;

    float a0 = t[base][j],     a1 = t[base][j + 1],     a2 = t[base][j + 2];
    float b0 = t[base + 1][j], b1 = t[base + 1][j + 1], b2 = t[base + 1][j + 2];
#pragma unroll
    for (int s = 0; s < 16; ++s) {
        const float* nr = &t[base + 2 + s][0];
        float n0 = nr[j], n1 = nr[j + 1], n2 = nr[j + 2];
        float acc = bz;
        acc += wv[0] * a0 + wv[1] * a1 + wv[2] * a2;
        acc += wv[3] * b0 + wv[4] * b1 + wv[5] * b2;
        acc += wv[6] * n0 + wv[7] * n1 + wv[8] * n2;
        op[(size_t)s * 128] = __float2half_rn(acc);
        a0 = b0; a1 = b1; a2 = b2;
        b0 = n0; b1 = n1; b2 = n2;
    }
}

// ---------------- Kernel 3a: partial channel-attn dots + sq over n-chunk ----
__global__ void __launch_bounds__(256) attn_partial_kernel()
{
    const int h = blockIdx.x, b = blockIdx.y, chunk = blockIdx.z;
    const int t = threadIdx.x;

    __shared__ float tile[4][8][132];
    __shared__ float red[256];

    const size_t base = (size_t)b * C3 * HW + (size_t)h * CH * HW;
    const __half* t_hq = g_dw[0] + base;
    const __half* t_lk = g_dw[1] + base + (size_t)CDIM * HW;
    const __half* t_lq = g_dw[1] + base;
    const __half* t_hk = g_dw[0] + base + (size_t)CDIM * HW;

    const int pairattn = t & 127;
    const int jp   = t >> 7;
    const int attn = pairattn >> 6;
    const int c    = (pairattn >> 3) & 7;
    const int d    = pairattn & 7;

    float acc = 0.f, sq = 0.f;
    const int col = t & 127;
    const int r0  = t >> 7;

    const int nbeg = chunk * 2048;
    for (int n0 = nbeg; n0 < nbeg + 2048; n0 += 128) {
#pragma unroll
        for (int it = 0; it < 16; ++it) {
            const int tens = it >> 2;
            const int row  = (r0 + 2 * it) & 7;
            const __half* src = (tens == 0) ? t_hq : (tens == 1) ? t_lk
                              : (tens == 2) ? t_lq : t_hk;
            tile[tens][row][col] = __half2float(__ldg(src + (size_t)row * HW + n0 + col));
        }
        __syncthreads();

        const float* qrow = &tile[attn * 2][c][0];
        const float* krow = &tile[attn * 2 + 1][d][0];
#pragma unroll 8
        for (int jj = jp * 64; jj < jp * 64 + 64; ++jj)
            acc += qrow[jj] * krow[jj];

        if (t < 32) {
            const float* rr = &tile[t >> 3][t & 7][0];
#pragma unroll 8
            for (int jj = 0; jj < 128; ++jj) sq += rr[jj] * rr[jj];
        }
        __syncthreads();
    }

    red[t] = acc;
    __syncthreads();
    float* gp = g_part + (((size_t)chunk * BATCH + b) * HEADS + h) * 160;
    if (t < 128) gp[t] = red[t] + red[t + 128];
    if (t < 32)  gp[128 + t] = sq;
}

// ---------------- Kernel 3b: finalize attention scores ----------------
__global__ void __launch_bounds__(128) attn_final_kernel(
    const float* __restrict__ temp1, const float* __restrict__ temp2)
{
    const int h = blockIdx.x, b = blockIdx.y, t = threadIdx.x;
    __shared__ float invn[32];

    float dot = 0.f;
#pragma unroll
    for (int chv = 0; chv < 8; ++chv)
        dot += g_part[(((size_t)chv * BATCH + b) * HEADS + h) * 160 + t];
    if (t < 32) {
        float sq = 0.f;
#pragma unroll
        for (int chv = 0; chv < 8; ++chv)
            sq += g_part[(((size_t)chv * BATCH + b) * HEADS + h) * 160 + 128 + t];
        invn[t] = 1.f / fmaxf(sqrtf(sq), EPSN);
    }
    __syncthreads();
    const int attn = t >> 6, c = (t >> 3) & 7, d = t & 7;
    float tmp = attn ? __ldg(temp2 + h) : __ldg(temp1 + h);
    float scale = invn[(attn * 2) * 8 + c] * invn[(attn * 2 + 1) * 8 + d] * tmp;
    g_attn[(((size_t)attn * BATCH + b) * HEADS + h) * 64 + c * 8 + d] = dot * scale;
}

// ---------------- Kernel 4: conv fusion + BN + ReLU + softmax ----------------
__global__ void __launch_bounds__(512) fuse_kernel(
    const float* __restrict__ pw, const float* __restrict__ pb,
    const float* __restrict__ gamma, const float* __restrict__ beta,
    const float* __restrict__ mean, const float* __restrict__ var)
{
    const int b = blockIdx.x;
    const int t = threadIdx.x;
    __shared__ float a1s[HEADS * 64];
    __shared__ float a2s[HEADS * 64];

#pragma unroll
    for (int it = 0; it < 8; ++it) {
        int idx = t + it * 512;
        a1s[idx] = g_attn[(size_t)b * 4096 + idx];
        a2s[idx] = g_attn[((size_t)BATCH + b) * 4096 + idx];
    }
    __syncthreads();

    const int ho = t >> 3;
    const int c  = t & 7;
    float f[8] = {0, 0, 0, 0, 0, 0, 0, 0};
    for (int hi = 0; hi < 64; ++hi) {
        float w1 = __ldg(pw + ho * 128 + hi);
        float w2 = __ldg(pw + ho * 128 + 64 + hi);
#pragma unroll
        for (int dd = 0; dd < 8; ++dd) {
            f[dd] += w1 * a1s[hi * 64 + c * 8 + dd];
            f[dd] += w2 * a2s[hi * 64 + c * 8 + dd];
        }
    }
    const float inv_std = rsqrtf(__ldg(var + ho) + EPSBN);
    const float g = __ldg(gamma + ho), bb = __ldg(beta + ho);
    const float mu = __ldg(mean + ho), pbi = __ldg(pb + ho);
#pragma unroll
    for (int dd = 0; dd < 8; ++dd)
        f[dd] = fmaxf((f[dd] + pbi - mu) * inv_std * g + bb, 0.f);

#pragma unroll
    for (int which = 0; which < 2; ++which) {
        const float* as = which ? a2s : a1s;
        float s[8], mx = -1e30f;
#pragma unroll
        for (int dd = 0; dd < 8; ++dd) {
            s[dd] = f[dd] + as[ho * 64 + c * 8 + dd];
            mx = fmaxf(mx, s[dd]);
        }
        float sum = 0.f;
#pragma unroll
        for (int dd = 0; dd < 8; ++dd) { s[dd] = expf(s[dd] - mx); sum += s[dd]; }
        float inv = 1.f / sum;
#pragma unroll
        for (int dd = 0; dd < 8; ++dd)
            g_aw[((size_t)which * BATCH + b) * 4096 + t * 8 + dd] = s[dd] * inv;
    }
}

// ---------------- Kernel 5: output einsum + residuals (float4/fp16 v) ------
__global__ void __launch_bounds__(256) out_kernel(
    const float* __restrict__ hsi, const float* __restrict__ lidar,
    float* __restrict__ out)
{
    const int h   = blockIdx.y;
    const int zz  = blockIdx.z;
    const int mod = zz >> 1;
    const int b   = zz & 1;
    const int t   = threadIdx.x;

    __shared__ float aw[64];
    if (t < 64)
        aw[t] = g_aw[(((size_t)mod * BATCH + b) * HEADS + h) * 64 + t];
    __syncthreads();

    const __half* vsrc = g_dw[mod] + ((size_t)b * C3 + 2 * CDIM + h * CH) * HW;
    const float* xin  = (mod ? lidar : hsi) + ((size_t)b * CDIM + h * CH) * HW;
    float* o = out + (size_t)mod * BATCH * CDIM * HW + ((size_t)b * CDIM + h * CH) * HW;

    const int n = (blockIdx.x * 256 + t) * 4;
    float4 v[8];
#pragma unroll
    for (int dd = 0; dd < 8; ++dd) {
        uint2 raw = *(const uint2*)(vsrc + (size_t)dd * HW + n);
        float2 f01 = __half22float2(*(__half2*)&raw.x);
        float2 f23 = __half22float2(*(__half2*)&raw.y);
        v[dd] = make_float4(f01.x, f01.y, f23.x, f23.y);
    }

#pragma unroll
    for (int c = 0; c < 8; ++c) {
        float4 s = *(const float4*)(xin + (size_t)c * HW + n);
        s.x += v[c].x; s.y += v[c].y; s.z += v[c].z; s.w += v[c].w;
#pragma unroll
        for (int dd = 0; dd < 8; ++dd) {
            const float a = aw[c * 8 + dd];
            s.x += a * v[dd].x; s.y += a * v[dd].y;
            s.z += a * v[dd].z; s.w += a * v[dd].w;
        }
        *(float4*)(o + (size_t)c * HW + n) = s;
    }
}

// ---------------- launch ----------------
extern "C" void kernel_launch(void* const* d_in, const int* in_sizes, int n_in,
                              void* d_out, int out_size)
{
    const float* hsi        = (const float*)d_in[0];
    const float* lidar      = (const float*)d_in[1];
    const float* hsi_qkv_w  = (const float*)d_in[2];
    const float* hsi_qkv_b  = (const float*)d_in[3];
    const float* lidar_qkv_w= (const float*)d_in[4];
    const float* lidar_qkv_b= (const float*)d_in[5];
    const float* hsi_dw_w   = (const float*)d_in[6];
    const float* hsi_dw_b   = (const float*)d_in[7];
    const float* lidar_dw_w = (const float*)d_in[8];
    const float* lidar_dw_b = (const float*)d_in[9];
    const float* temp1      = (const float*)d_in[10];
    const float* temp2      = (const float*)d_in[11];
    const float* proj_w     = (const float*)d_in[12];
    const float* proj_b     = (const float*)d_in[13];
    const float* bn_gamma   = (const float*)d_in[14];
    const float* bn_beta    = (const float*)d_in[15];
    const float* bn_mean    = (const float*)d_in[16];
    const float* bn_var     = (const float*)d_in[17];
    float* out = (float*)d_out;

    static int smem_set = 0;
    if (!smem_set) {
        cudaFuncSetAttribute(qkv_gemm_mma,
                             cudaFuncAttributeMaxDynamicSharedMemorySize, GEMM_SMEM);
        smem_set = 1;
    }

    __half *wf, *xh, *xl;
    cudaGetSymbolAddress((void**)&wf, g_wf);
    cudaGetSymbolAddress((void**)&xh, g_xh);
    cudaGetSymbolAddress((void**)&xl, g_xl);

    const int w4 = C3 * CDIM / 4;
    const int x4 = BATCH * CDIM * HW / 4;

    dim3 ggrid(HW / 128, C3 / 128, BATCH);
    dim3 dgrid(4, C3, BATCH);

    // modality 0 (hsi)
    cvt_w<<<(w4 + 255) / 256, 256>>>(hsi_qkv_w, wf, w4);
    cvt_split_x<<<(x4 + 255) / 256, 256>>>(hsi, xh, xl, x4);
    qkv_gemm_mma<<<ggrid, 256, GEMM_SMEM>>>(hsi_qkv_b);
    dwconv_kernel<<<dgrid, 256>>>(hsi_dw_w, hsi_dw_b, 0);

    // modality 1 (lidar)
    cvt_w<<<(w4 + 255) / 256, 256>>>(lidar_qkv_w, wf, w4);
    cvt_split_x<<<(x4 + 255) / 256, 256>>>(lidar, xh, xl, x4);
    qkv_gemm_mma<<<ggrid, 256, GEMM_SMEM>>>(lidar_qkv_b);
    dwconv_kernel<<<dgrid, 256>>>(lidar_dw_w, lidar_dw_b, 1);

    attn_partial_kernel<<<dim3(HEADS, BATCH, 8), 256>>>();
    attn_final_kernel<<<dim3(HEADS, BATCH), 128>>>(temp1, temp2);
    fuse_kernel<<<BATCH, 512>>>(proj_w, proj_b, bn_gamma, bn_beta, bn_mean, bn_var);
    out_kernel<<<dim3(HW / 1024, HEADS, BATCH * 2), 256>>>(hsi, lidar, out);
}

// round 8
// speedup vs baseline: 4.9830x; 1.4232x over previous
#include <cuda_runtime.h>
#include <cuda_fp16.h>
#include <cstdint>
#include <math.h>

// ---------------- problem constants ----------------
#define BATCH   2
#define CDIM    512
#define C3      1536
#define HW      16384
#define HEADS   64
#define CH      8
#define EPSN    1e-12f
#define EPSBN   1e-5f

// ---------------- scratch ----------------
__device__ __half g_qkv[BATCH * C3 * HW];                // qkv conv out (fp16)
__device__ __half g_dw[2][BATCH * C3 * HW];              // post-dwconv q/k/v (fp16)
__device__ float g_part[8 * BATCH * HEADS * 160];        // partial dots(128)+sq(32)
__device__ float g_attn[2 * BATCH * HEADS * CH * CH];
__device__ float g_aw[2 * BATCH * HEADS * CH * CH];
__device__ __half g_wf[C3 * CDIM];                       // w fp16
__device__ __half g_xh[BATCH * CDIM * HW];               // x fp16

// ---------------- PTX helpers (sm_80-era, valid on plain sm_103 target) -----
__device__ __forceinline__ uint32_t smem_u32(const void* p) {
    uint32_t a;
    asm("{ .reg .u64 t; cvta.to.shared.u64 t, %1; cvt.u32.u64 %0, t; }" : "=r"(a) : "l"(p));
    return a;
}
__device__ __forceinline__ void cpasync16(uint32_t saddr, const void* g) {
    asm volatile("cp.async.cg.shared.global [%0], [%1], 16;" :: "r"(saddr), "l"(g));
}
__device__ __forceinline__ void ldsm4(uint32_t addr, uint32_t* r) {
    asm volatile("ldmatrix.sync.aligned.m8n8.x4.shared.b16 {%0,%1,%2,%3}, [%4];"
        : "=r"(r[0]), "=r"(r[1]), "=r"(r[2]), "=r"(r[3]) : "r"(addr));
}
__device__ __forceinline__ void ldsm4t(uint32_t addr, uint32_t* r) {
    asm volatile("ldmatrix.sync.aligned.m8n8.x4.trans.shared.b16 {%0,%1,%2,%3}, [%4];"
        : "=r"(r[0]), "=r"(r[1]), "=r"(r[2]), "=r"(r[3]) : "r"(addr));
}
__device__ __forceinline__ void mma16816(float* c, const uint32_t* a, const uint32_t* b) {
    asm volatile("mma.sync.aligned.m16n8k16.row.col.f32.f16.f16.f32 "
        "{%0,%1,%2,%3}, {%4,%5,%6,%7}, {%8,%9}, {%0,%1,%2,%3};"
        : "+f"(c[0]), "+f"(c[1]), "+f"(c[2]), "+f"(c[3])
        : "r"(a[0]), "r"(a[1]), "r"(a[2]), "r"(a[3]), "r"(b[0]), "r"(b[1]));
}

// ---------------- Kernel 0: fp32 -> fp16 convert ----------------
__global__ void __launch_bounds__(256) cvt_h(
    const float* __restrict__ src, __half* __restrict__ dh, int n4)
{
    int i = blockIdx.x * 256 + threadIdx.x;
    if (i >= n4) return;
    float4 v = ((const float4*)src)[i];
    __half h[4] = { __float2half_rn(v.x), __float2half_rn(v.y),
                    __float2half_rn(v.z), __float2half_rn(v.w) };
    ((uint2*)dh)[i] = *(uint2*)h;
}

// ---------------- Kernel 1: qkv GEMM, fp16 single-product, 3-stage ---------
// y[b][m][n] = bias[m] + sum_k w[m][k] x[b][k][n]
// CTA 128(M) x 128(N), BK=32, 3-stage cp.async, 8 warps (2m x 4n).
#define SM_A_STAGE 10240          // 128 rows * 80B (64B data + pad)
#define SM_B_BASE  30720          // after 3 A stages
#define SM_B_STAGE 8704           // 32 rows * 272B (256B data + pad)
#define GEMM_SMEM  56832

__device__ __forceinline__ void gemm_load_stage(
    uint32_t sb, int s, int k0, const __half* wp, const __half* xp, int tid)
{
    uint32_t a_h = sb + s * SM_A_STAGE;
    uint32_t b_h = sb + SM_B_BASE + s * SM_B_STAGE;
#pragma unroll
    for (int it = 0; it < 2; ++it) {
        int cid = tid + it * 256;
        int r = cid >> 2, c = cid & 3;
        cpasync16(a_h + r * 80 + c * 16, wp + (size_t)r * CDIM + k0 + c * 8);
    }
#pragma unroll
    for (int it = 0; it < 2; ++it) {
        int cid = tid + it * 256;
        int r = cid >> 4, c = cid & 15;
        cpasync16(b_h + r * 272 + c * 16, xp + (size_t)(k0 + r) * HW + c * 8);
    }
    asm volatile("cp.async.commit_group;");
}

__global__ void __launch_bounds__(256) qkv_gemm_mma(
    const float* __restrict__ bias)
{
    extern __shared__ char smem[];
    const uint32_t sb = smem_u32(smem);
    const int tid = threadIdx.x;
    const int warp = tid >> 5, lid = tid & 31;
    const int n0 = blockIdx.x * 128;
    const int m0 = blockIdx.y * 128;
    const int b  = blockIdx.z;

    const __half* wp = g_wf + (size_t)m0 * CDIM;
    const __half* xp = g_xh + (size_t)b * CDIM * HW + n0;

    float acc[4][4][4];
#pragma unroll
    for (int i = 0; i < 4; ++i)
#pragma unroll
        for (int j = 0; j < 4; ++j)
#pragma unroll
            for (int q = 0; q < 4; ++q) acc[i][j][q] = 0.f;

    const int wm = (warp & 1) * 64;
    const int wn = (warp >> 1) * 32;

    gemm_load_stage(sb, 0, 0, wp, xp, tid);
    gemm_load_stage(sb, 1, 32, wp, xp, tid);

    int s = 0;
    for (int ks = 0; ks < 16; ++ks) {
        if (ks == 15) asm volatile("cp.async.wait_group 0;");
        else          asm volatile("cp.async.wait_group 1;");
        __syncthreads();

        if (ks + 2 < 16) {
            int ld = s + 2; if (ld >= 3) ld -= 3;
            gemm_load_stage(sb, ld, (ks + 2) * 32, wp, xp, tid);
        }

        uint32_t a_h = sb + s * SM_A_STAGE;
        uint32_t b_h = sb + SM_B_BASE + s * SM_B_STAGE;

#pragma unroll
        for (int kf = 0; kf < 2; ++kf) {
            uint32_t ah[4][4], bh[2][4];
            const int arow = lid & 15;
            const int acol = kf * 16 + (lid >> 4) * 8;
#pragma unroll
            for (int mf = 0; mf < 4; ++mf) {
                uint32_t off = (uint32_t)((wm + mf * 16 + arow) * 80 + acol * 2);
                ldsm4(a_h + off, ah[mf]);
            }
            const int brow = kf * 16 + (lid & 15);
            const int bcol = (lid >> 4) * 8;
#pragma unroll
            for (int nf2 = 0; nf2 < 2; ++nf2) {
                uint32_t off = (uint32_t)(brow * 272 + (wn + nf2 * 16 + bcol) * 2);
                ldsm4t(b_h + off, bh[nf2]);
            }
#pragma unroll
            for (int mf = 0; mf < 4; ++mf)
#pragma unroll
                for (int nf = 0; nf < 4; ++nf)
                    mma16816(acc[mf][nf], ah[mf], &bh[nf >> 1][(nf & 1) * 2]);
        }
        ++s; if (s == 3) s = 0;
    }

    // epilogue: bias + fp16 stores
    __half* outp = g_qkv + (size_t)b * C3 * HW;
#pragma unroll
    for (int mf = 0; mf < 4; ++mf) {
        const int r = m0 + wm + mf * 16 + (lid >> 2);
        const float bv0 = __ldg(bias + r);
        const float bv1 = __ldg(bias + r + 8);
#pragma unroll
        for (int nf = 0; nf < 4; ++nf) {
            const int cc = n0 + wn + nf * 8 + 2 * (lid & 3);
            __half2 v0 = __floats2half2_rn(acc[mf][nf][0] + bv0, acc[mf][nf][1] + bv0);
            __half2 v1 = __floats2half2_rn(acc[mf][nf][2] + bv1, acc[mf][nf][3] + bv1);
            *(__half2*)(outp + (size_t)r * HW + cc) = v0;
            *(__half2*)(outp + (size_t)(r + 8) * HW + cc) = v1;
        }
    }
}

// ---------------- Kernel 2: depthwise 3x3, sliding-window, fp16 I/O --------
__global__ void __launch_bounds__(256) dwconv_kernel(
    const float* __restrict__ w, const float* __restrict__ bias, int mod)
{
    __shared__ float t[34][132];
    const int c = blockIdx.y, b = blockIdx.z;
    const int r0 = blockIdx.x * 32;
    const int tid = threadIdx.x;
    const __half* xc = g_qkv + ((size_t)b * C3 + c) * HW;

    for (int idx = tid; idx < 34 * 64; idx += 256) {
        int rr = idx >> 6, jp = idx & 63;
        int gr = r0 - 1 + rr;
        float2 f = make_float2(0.f, 0.f);
        if ((unsigned)gr < 128u)
            f = __half22float2(*(const __half2*)(xc + gr * 128 + jp * 2));
        t[rr][jp * 2 + 1] = f.x;
        t[rr][jp * 2 + 2] = f.y;
    }
    if (tid < 34) { t[tid][0] = 0.f; t[tid][129] = 0.f; }

    float wv[9];
#pragma unroll
    for (int k = 0; k < 9; ++k) wv[k] = __ldg(w + c * 9 + k);
    const float bz = __ldg(bias + c);
    __syncthreads();

    const int j = tid & 127;
    const int base = (tid >> 7) * 16;
    __half* op = g_dw[mod] + ((size_t)b * C3 + c) * HW + (size_t)(r0 + base) * 128 + j;

    float a0 = t[base][j],     a1 = t[base][j + 1],     a2 = t[base][j + 2];
    float b0 = t[base + 1][j], b1 = t[base + 1][j + 1], b2 = t[base + 1][j + 2];
#pragma unroll
    for (int s = 0; s < 16; ++s) {
        const float* nr = &t[base + 2 + s][0];
        float n0 = nr[j], n1 = nr[j + 1], n2 = nr[j + 2];
        float acc = bz;
        acc += wv[0] * a0 + wv[1] * a1 + wv[2] * a2;
        acc += wv[3] * b0 + wv[4] * b1 + wv[5] * b2;
        acc += wv[6] * n0 + wv[7] * n1 + wv[8] * n2;
        op[(size_t)s * 128] = __float2half_rn(acc);
        a0 = b0; a1 = b1; a2 = b2;
        b0 = n0; b1 = n1; b2 = n2;
    }
}

// ---------------- Kernel 3a: partial channel-attn dots + sq over n-chunk ----
__global__ void __launch_bounds__(256) attn_partial_kernel()
{
    const int h = blockIdx.x, b = blockIdx.y, chunk = blockIdx.z;
    const int t = threadIdx.x;

    __shared__ float tile[4][8][132];
    __shared__ float red[256];

    const size_t base = (size_t)b * C3 * HW + (size_t)h * CH * HW;
    const __half* t_hq = g_dw[0] + base;
    const __half* t_lk = g_dw[1] + base + (size_t)CDIM * HW;
    const __half* t_lq = g_dw[1] + base;
    const __half* t_hk = g_dw[0] + base + (size_t)CDIM * HW;

    const int pairattn = t & 127;
    const int jp   = t >> 7;
    const int attn = pairattn >> 6;
    const int c    = (pairattn >> 3) & 7;
    const int d    = pairattn & 7;

    float acc = 0.f, sq = 0.f;
    const int col = t & 127;
    const int r0  = t >> 7;

    const int nbeg = chunk * 2048;
    for (int n0 = nbeg; n0 < nbeg + 2048; n0 += 128) {
#pragma unroll
        for (int it = 0; it < 16; ++it) {
            const int tens = it >> 2;
            const int row  = (r0 + 2 * it) & 7;
            const __half* src = (tens == 0) ? t_hq : (tens == 1) ? t_lk
                              : (tens == 2) ? t_lq : t_hk;
            tile[tens][row][col] = __half2float(__ldg(src + (size_t)row * HW + n0 + col));
        }
        __syncthreads();

        const float* qrow = &tile[attn * 2][c][0];
        const float* krow = &tile[attn * 2 + 1][d][0];
#pragma unroll 8
        for (int jj = jp * 64; jj < jp * 64 + 64; ++jj)
            acc += qrow[jj] * krow[jj];

        if (t < 32) {
            const float* rr = &tile[t >> 3][t & 7][0];
#pragma unroll 8
            for (int jj = 0; jj < 128; ++jj) sq += rr[jj] * rr[jj];
        }
        __syncthreads();
    }

    red[t] = acc;
    __syncthreads();
    float* gp = g_part + (((size_t)chunk * BATCH + b) * HEADS + h) * 160;
    if (t < 128) gp[t] = red[t] + red[t + 128];
    if (t < 32)  gp[128 + t] = sq;
}

// ---------------- Kernel 3b: finalize attention scores ----------------
__global__ void __launch_bounds__(128) attn_final_kernel(
    const float* __restrict__ temp1, const float* __restrict__ temp2)
{
    const int h = blockIdx.x, b = blockIdx.y, t = threadIdx.x;
    __shared__ float invn[32];

    float dot = 0.f;
#pragma unroll
    for (int chv = 0; chv < 8; ++chv)
        dot += g_part[(((size_t)chv * BATCH + b) * HEADS + h) * 160 + t];
    if (t < 32) {
        float sq = 0.f;
#pragma unroll
        for (int chv = 0; chv < 8; ++chv)
            sq += g_part[(((size_t)chv * BATCH + b) * HEADS + h) * 160 + 128 + t];
        invn[t] = 1.f / fmaxf(sqrtf(sq), EPSN);
    }
    __syncthreads();
    const int attn = t >> 6, c = (t >> 3) & 7, d = t & 7;
    float tmp = attn ? __ldg(temp2 + h) : __ldg(temp1 + h);
    float scale = invn[(attn * 2) * 8 + c] * invn[(attn * 2 + 1) * 8 + d] * tmp;
    g_attn[(((size_t)attn * BATCH + b) * HEADS + h) * 64 + c * 8 + d] = dot * scale;
}

// ---------------- Kernel 4: conv fusion + BN + ReLU + softmax ----------------
__global__ void __launch_bounds__(512) fuse_kernel(
    const float* __restrict__ pw, const float* __restrict__ pb,
    const float* __restrict__ gamma, const float* __restrict__ beta,
    const float* __restrict__ mean, const float* __restrict__ var)
{
    const int b = blockIdx.x;
    const int t = threadIdx.x;
    __shared__ float a1s[HEADS * 64];
    __shared__ float a2s[HEADS * 64];

#pragma unroll
    for (int it = 0; it < 8; ++it) {
        int idx = t + it * 512;
        a1s[idx] = g_attn[(size_t)b * 4096 + idx];
        a2s[idx] = g_attn[((size_t)BATCH + b) * 4096 + idx];
    }
    __syncthreads();

    const int ho = t >> 3;
    const int c  = t & 7;
    float f[8] = {0, 0, 0, 0, 0, 0, 0, 0};
    for (int hi = 0; hi < 64; ++hi) {
        float w1 = __ldg(pw + ho * 128 + hi);
        float w2 = __ldg(pw + ho * 128 + 64 + hi);
#pragma unroll
        for (int dd = 0; dd < 8; ++dd) {
            f[dd] += w1 * a1s[hi * 64 + c * 8 + dd];
            f[dd] += w2 * a2s[hi * 64 + c * 8 + dd];
        }
    }
    const float inv_std = rsqrtf(__ldg(var + ho) + EPSBN);
    const float g = __ldg(gamma + ho), bb = __ldg(beta + ho);
    const float mu = __ldg(mean + ho), pbi = __ldg(pb + ho);
#pragma unroll
    for (int dd = 0; dd < 8; ++dd)
        f[dd] = fmaxf((f[dd] + pbi - mu) * inv_std * g + bb, 0.f);

#pragma unroll
    for (int which = 0; which < 2; ++which) {
        const float* as = which ? a2s : a1s;
        float s[8], mx = -1e30f;
#pragma unroll
        for (int dd = 0; dd < 8; ++dd) {
            s[dd] = f[dd] + as[ho * 64 + c * 8 + dd];
            mx = fmaxf(mx, s[dd]);
        }
        float sum = 0.f;
#pragma unroll
        for (int dd = 0; dd < 8; ++dd) { s[dd] = expf(s[dd] - mx); sum += s[dd]; }
        float inv = 1.f / sum;
#pragma unroll
        for (int dd = 0; dd < 8; ++dd)
            g_aw[((size_t)which * BATCH + b) * 4096 + t * 8 + dd] = s[dd] * inv;
    }
}

// ---------------- Kernel 5: output einsum + residuals (float4/fp16 v) ------
__global__ void __launch_bounds__(256) out_kernel(
    const float* __restrict__ hsi, const float* __restrict__ lidar,
    float* __restrict__ out)
{
    const int h   = blockIdx.y;
    const int zz  = blockIdx.z;
    const int mod = zz >> 1;
    const int b   = zz & 1;
    const int t   = threadIdx.x;

    __shared__ float aw[64];
    if (t < 64)
        aw[t] = g_aw[(((size_t)mod * BATCH + b) * HEADS + h) * 64 + t];
    __syncthreads();

    const __half* vsrc = g_dw[mod] + ((size_t)b * C3 + 2 * CDIM + h * CH) * HW;
    const float* xin  = (mod ? lidar : hsi) + ((size_t)b * CDIM + h * CH) * HW;
    float* o = out + (size_t)mod * BATCH * CDIM * HW + ((size_t)b * CDIM + h * CH) * HW;

    const int n = (blockIdx.x * 256 + t) * 4;
    float4 v[8];
#pragma unroll
    for (int dd = 0; dd < 8; ++dd) {
        uint2 raw = *(const uint2*)(vsrc + (size_t)dd * HW + n);
        float2 f01 = __half22float2(*(__half2*)&raw.x);
        float2 f23 = __half22float2(*(__half2*)&raw.y);
        v[dd] = make_float4(f01.x, f01.y, f23.x, f23.y);
    }

#pragma unroll
    for (int c = 0; c < 8; ++c) {
        float4 s = *(const float4*)(xin + (size_t)c * HW + n);
        s.x += v[c].x; s.y += v[c].y; s.z += v[c].z; s.w += v[c].w;
#pragma unroll
        for (int dd = 0; dd < 8; ++dd) {
            const float a = aw[c * 8 + dd];
            s.x += a * v[dd].x; s.y += a * v[dd].y;
            s.z += a * v[dd].z; s.w += a * v[dd].w;
        }
        *(float4*)(o + (size_t)c * HW + n) = s;
    }
}

// ---------------- launch ----------------
extern "C" void kernel_launch(void* const* d_in, const int* in_sizes, int n_in,
                              void* d_out, int out_size)
{
    const float* hsi        = (const float*)d_in[0];
    const float* lidar      = (const float*)d_in[1];
    const float* hsi_qkv_w  = (const float*)d_in[2];
    const float* hsi_qkv_b  = (const float*)d_in[3];
    const float* lidar_qkv_w= (const float*)d_in[4];
    const float* lidar_qkv_b= (const float*)d_in[5];
    const float* hsi_dw_w   = (const float*)d_in[6];
    const float* hsi_dw_b   = (const float*)d_in[7];
    const float* lidar_dw_w = (const float*)d_in[8];
    const float* lidar_dw_b = (const float*)d_in[9];
    const float* temp1      = (const float*)d_in[10];
    const float* temp2      = (const float*)d_in[11];
    const float* proj_w     = (const float*)d_in[12];
    const float* proj_b     = (const float*)d_in[13];
    const float* bn_gamma   = (const float*)d_in[14];
    const float* bn_beta    = (const float*)d_in[15];
    const float* bn_mean    = (const float*)d_in[16];
    const float* bn_var     = (const float*)d_in[17];
    float* out = (float*)d_out;

    static int smem_set = 0;
    if (!smem_set) {
        cudaFuncSetAttribute(qkv_gemm_mma,
                             cudaFuncAttributeMaxDynamicSharedMemorySize, GEMM_SMEM);
        smem_set = 1;
    }

    __half *wf, *xh;
    cudaGetSymbolAddress((void**)&wf, g_wf);
    cudaGetSymbolAddress((void**)&xh, g_xh);

    const int w4 = C3 * CDIM / 4;
    const int x4 = BATCH * CDIM * HW / 4;

    dim3 ggrid(HW / 128, C3 / 128, BATCH);
    dim3 dgrid(4, C3, BATCH);

    // modality 0 (hsi)
    cvt_h<<<(w4 + 255) / 256, 256>>>(hsi_qkv_w, wf, w4);
    cvt_h<<<(x4 + 255) / 256, 256>>>(hsi, xh, x4);
    qkv_gemm_mma<<<ggrid, 256, GEMM_SMEM>>>(hsi_qkv_b);
    dwconv_kernel<<<dgrid, 256>>>(hsi_dw_w, hsi_dw_b, 0);

    // modality 1 (lidar)
    cvt_h<<<(w4 + 255) / 256, 256>>>(lidar_qkv_w, wf, w4);
    cvt_h<<<(x4 + 255) / 256, 256>>>(lidar, xh, x4);
    qkv_gemm_mma<<<ggrid, 256, GEMM_SMEM>>>(lidar_qkv_b);
    dwconv_kernel<<<dgrid, 256>>>(lidar_dw_w, lidar_dw_b, 1);

    attn_partial_kernel<<<dim3(HEADS, BATCH, 8), 256>>>();
    attn_final_kernel<<<dim3(HEADS, BATCH), 128>>>(temp1, temp2);
    fuse_kernel<<<BATCH, 512>>>(proj_w, proj_b, bn_gamma, bn_beta, bn_mean, bn_var);
    out_kernel<<<dim3(HW / 1024, HEADS, BATCH * 2), 256>>>(hsi, lidar, out);
}

// round 10
// speedup vs baseline: 5.1488x; 1.0333x over previous
#include <cuda_runtime.h>
#include <cuda_fp16.h>
#include <cstdint>
#include <math.h>

// ---------------- problem constants ----------------
#define BATCH   2
#define CDIM    512
#define C3      1536
#define HW      16384
#define HEADS   64
#define CH      8
#define EPSN    1e-12f
#define EPSBN   1e-5f

// ---------------- scratch ----------------
__device__ __half g_qkv[BATCH * C3 * HW];                // qkv conv out (fp16)
__device__ __half g_dw[2][BATCH * C3 * HW];              // post-dwconv q/k/v (fp16)
__device__ float g_part[8 * BATCH * HEADS * 160];        // partial dots(128)+sq(32)
__device__ float g_attn[2 * BATCH * HEADS * CH * CH];
__device__ float g_aw[2 * BATCH * HEADS * CH * CH];
__device__ __half g_wf[C3 * CDIM];                       // w fp16
__device__ __half g_xh[BATCH * CDIM * HW];               // x fp16

// ---------------- PTX helpers (sm_80-era, valid on plain sm_103 target) -----
__device__ __forceinline__ uint32_t smem_u32(const void* p) {
    uint32_t a;
    asm("{ .reg .u64 t; cvta.to.shared.u64 t, %1; cvt.u32.u64 %0, t; }" : "=r"(a) : "l"(p));
    return a;
}
__device__ __forceinline__ void cpasync16(uint32_t saddr, const void* g) {
    asm volatile("cp.async.cg.shared.global [%0], [%1], 16;" :: "r"(saddr), "l"(g));
}
__device__ __forceinline__ void ldsm4(uint32_t addr, uint32_t* r) {
    asm volatile("ldmatrix.sync.aligned.m8n8.x4.shared.b16 {%0,%1,%2,%3}, [%4];"
        : "=r"(r[0]), "=r"(r[1]), "=r"(r[2]), "=r"(r[3]) : "r"(addr));
}
__device__ __forceinline__ void ldsm4t(uint32_t addr, uint32_t* r) {
    asm volatile("ldmatrix.sync.aligned.m8n8.x4.trans.shared.b16 {%0,%1,%2,%3}, [%4];"
        : "=r"(r[0]), "=r"(r[1]), "=r"(r[2]), "=r"(r[3]) : "r"(addr));
}
__device__ __forceinline__ void mma16816(float* c, const uint32_t* a, const uint32_t* b) {
    asm volatile("mma.sync.aligned.m16n8k16.row.col.f32.f16.f16.f32 "
        "{%0,%1,%2,%3}, {%4,%5,%6,%7}, {%8,%9}, {%0,%1,%2,%3};"
        : "+f"(c[0]), "+f"(c[1]), "+f"(c[2]), "+f"(c[3])
        : "r"(a[0]), "r"(a[1]), "r"(a[2]), "r"(a[3]), "r"(b[0]), "r"(b[1]));
}

// ---------------- Kernel 0: fp32 -> fp16 convert ----------------
__global__ void __launch_bounds__(256) cvt_h(
    const float* __restrict__ src, __half* __restrict__ dh, int n4)
{
    int i = blockIdx.x * 256 + threadIdx.x;
    if (i >= n4) return;
    float4 v = ((const float4*)src)[i];
    __half h[4] = { __float2half_rn(v.x), __float2half_rn(v.y),
                    __float2half_rn(v.z), __float2half_rn(v.w) };
    ((uint2*)dh)[i] = *(uint2*)h;
}

// ---------------- Kernel 1: qkv GEMM, fp16 single-product, 3-stage ---------
#define SM_A_STAGE 10240          // 128 rows * 80B (64B data + pad)
#define SM_B_BASE  30720          // after 3 A stages
#define SM_B_STAGE 8704           // 32 rows * 272B (256B data + pad)
#define GEMM_SMEM  56832

__device__ __forceinline__ void gemm_load_stage(
    uint32_t sb, int s, int k0, const __half* wp, const __half* xp, int tid)
{
    uint32_t a_h = sb + s * SM_A_STAGE;
    uint32_t b_h = sb + SM_B_BASE + s * SM_B_STAGE;
#pragma unroll
    for (int it = 0; it < 2; ++it) {
        int cid = tid + it * 256;
        int r = cid >> 2, c = cid & 3;
        cpasync16(a_h + r * 80 + c * 16, wp + (size_t)r * CDIM + k0 + c * 8);
    }
#pragma unroll
    for (int it = 0; it < 2; ++it) {
        int cid = tid + it * 256;
        int r = cid >> 4, c = cid & 15;
        cpasync16(b_h + r * 272 + c * 16, xp + (size_t)(k0 + r) * HW + c * 8);
    }
    asm volatile("cp.async.commit_group;");
}

__global__ void __launch_bounds__(256) qkv_gemm_mma(
    const float* __restrict__ bias)
{
    extern __shared__ char smem[];
    const uint32_t sb = smem_u32(smem);
    const int tid = threadIdx.x;
    const int warp = tid >> 5, lid = tid & 31;
    const int n0 = blockIdx.x * 128;
    const int m0 = blockIdx.y * 128;
    const int b  = blockIdx.z;

    const __half* wp = g_wf + (size_t)m0 * CDIM;
    const __half* xp = g_xh + (size_t)b * CDIM * HW + n0;

    float acc[4][4][4];
#pragma unroll
    for (int i = 0; i < 4; ++i)
#pragma unroll
        for (int j = 0; j < 4; ++j)
#pragma unroll
            for (int q = 0; q < 4; ++q) acc[i][j][q] = 0.f;

    const int wm = (warp & 1) * 64;
    const int wn = (warp >> 1) * 32;

    gemm_load_stage(sb, 0, 0, wp, xp, tid);
    gemm_load_stage(sb, 1, 32, wp, xp, tid);

    int s = 0;
    for (int ks = 0; ks < 16; ++ks) {
        if (ks == 15) asm volatile("cp.async.wait_group 0;");
        else          asm volatile("cp.async.wait_group 1;");
        __syncthreads();

        if (ks + 2 < 16) {
            int ld = s + 2; if (ld >= 3) ld -= 3;
            gemm_load_stage(sb, ld, (ks + 2) * 32, wp, xp, tid);
        }

        uint32_t a_h = sb + s * SM_A_STAGE;
        uint32_t b_h = sb + SM_B_BASE + s * SM_B_STAGE;

#pragma unroll
        for (int kf = 0; kf < 2; ++kf) {
            uint32_t ah[4][4], bh[2][4];
            const int arow = lid & 15;
            const int acol = kf * 16 + (lid >> 4) * 8;
#pragma unroll
            for (int mf = 0; mf < 4; ++mf) {
                uint32_t off = (uint32_t)((wm + mf * 16 + arow) * 80 + acol * 2);
                ldsm4(a_h + off, ah[mf]);
            }
            const int brow = kf * 16 + (lid & 15);
            const int bcol = (lid >> 4) * 8;
#pragma unroll
            for (int nf2 = 0; nf2 < 2; ++nf2) {
                uint32_t off = (uint32_t)(brow * 272 + (wn + nf2 * 16 + bcol) * 2);
                ldsm4t(b_h + off, bh[nf2]);
            }
#pragma unroll
            for (int mf = 0; mf < 4; ++mf)
#pragma unroll
                for (int nf = 0; nf < 4; ++nf)
                    mma16816(acc[mf][nf], ah[mf], &bh[nf >> 1][(nf & 1) * 2]);
        }
        ++s; if (s == 3) s = 0;
    }

    // epilogue: bias + fp16 stores
    __half* outp = g_qkv + (size_t)b * C3 * HW;
#pragma unroll
    for (int mf = 0; mf < 4; ++mf) {
        const int r = m0 + wm + mf * 16 + (lid >> 2);
        const float bv0 = __ldg(bias + r);
        const float bv1 = __ldg(bias + r + 8);
#pragma unroll
        for (int nf = 0; nf < 4; ++nf) {
            const int cc = n0 + wn + nf * 8 + 2 * (lid & 3);
            __half2 v0 = __floats2half2_rn(acc[mf][nf][0] + bv0, acc[mf][nf][1] + bv0);
            __half2 v1 = __floats2half2_rn(acc[mf][nf][2] + bv1, acc[mf][nf][3] + bv1);
            *(__half2*)(outp + (size_t)r * HW + cc) = v0;
            *(__half2*)(outp + (size_t)(r + 8) * HW + cc) = v1;
        }
    }
}

// ---------------- Kernel 2: depthwise 3x3, 2 cols/thread, fp16 I/O ---------
// tile data for input col c lives at index c+1; cols 0 and 129 are zero guards.
__global__ void __launch_bounds__(256) dwconv_kernel(
    const float* __restrict__ w, const float* __restrict__ bias, int mod)
{
    __shared__ float t[34][132];
    const int c = blockIdx.y, b = blockIdx.z;
    const int r0 = blockIdx.x * 32;
    const int tid = threadIdx.x;
    const __half* xc = g_qkv + ((size_t)b * C3 + c) * HW;

    for (int idx = tid; idx < 34 * 64; idx += 256) {
        int rr = idx >> 6, jp = idx & 63;
        int gr = r0 - 1 + rr;
        float2 f = make_float2(0.f, 0.f);
        if ((unsigned)gr < 128u)
            f = __half22float2(*(const __half2*)(xc + gr * 128 + jp * 2));
        t[rr][jp * 2 + 1] = f.x;
        t[rr][jp * 2 + 2] = f.y;
    }
    if (tid < 34) { t[tid][0] = 0.f; t[tid][129] = 0.f; }

    float wv[9];
#pragma unroll
    for (int k = 0; k < 9; ++k) wv[k] = __ldg(w + c * 9 + k);
    const float bz = __ldg(bias + c);
    __syncthreads();

    const int p  = (tid & 63) * 2;      // output col pair base
    const int rb = (tid >> 6) * 8;      // row group base within strip
    __half* op = g_dw[mod] + ((size_t)b * C3 + c) * HW + (size_t)(r0 + rb) * 128 + p;

    // output col p needs tile idx p..p+2; col p+1 needs p+1..p+3
    float2 A0 = *(const float2*)&t[rb][p];
    float2 A1 = *(const float2*)&t[rb][p + 2];
    float2 B0 = *(const float2*)&t[rb + 1][p];
    float2 B1 = *(const float2*)&t[rb + 1][p + 2];
#pragma unroll
    for (int s = 0; s < 8; ++s) {
        float2 N0 = *(const float2*)&t[rb + 2 + s][p];
        float2 N1 = *(const float2*)&t[rb + 2 + s][p + 2];
        float acc0 = bz + wv[0] * A0.x + wv[1] * A0.y + wv[2] * A1.x
                        + wv[3] * B0.x + wv[4] * B0.y + wv[5] * B1.x
                        + wv[6] * N0.x + wv[7] * N0.y + wv[8] * N1.x;
        float acc1 = bz + wv[0] * A0.y + wv[1] * A1.x + wv[2] * A1.y
                        + wv[3] * B0.y + wv[4] * B1.x + wv[5] * B1.y
                        + wv[6] * N0.y + wv[7] * N1.x + wv[8] * N1.y;
        *(__half2*)(op + (size_t)s * 128) = __floats2half2_rn(acc0, acc1);
        A0 = B0; A1 = B1;
        B0 = N0; B1 = N1;
    }
}

// ---------------- Kernel 3a: partial channel-attn dots + sq over n-chunk ----
__global__ void __launch_bounds__(256) attn_partial_kernel()
{
    const int h = blockIdx.x, b = blockIdx.y, chunk = blockIdx.z;
    const int t = threadIdx.x;

    __shared__ float tile[4][8][132];
    __shared__ float red[256];

    const size_t base = (size_t)b * C3 * HW + (size_t)h * CH * HW;
    const __half* t_hq = g_dw[0] + base;
    const __half* t_lk = g_dw[1] + base + (size_t)CDIM * HW;
    const __half* t_lq = g_dw[1] + base;
    const __half* t_hk = g_dw[0] + base + (size_t)CDIM * HW;

    const int pairattn = t & 127;
    const int jp   = t >> 7;
    const int attn = pairattn >> 6;
    const int c    = (pairattn >> 3) & 7;
    const int d    = pairattn & 7;

    float acc = 0.f, sq = 0.f;
    const int col2 = t & 63;            // half2 column index
    const int rsel = t >> 6;            // 0..3

    const int nbeg = chunk * 2048;
    for (int n0 = nbeg; n0 < nbeg + 2048; n0 += 128) {
        // fill tile: 4 tensors x 8 rows x 64 half2, 8 iters of 256 threads
#pragma unroll
        for (int it = 0; it < 8; ++it) {
            const int tens = it >> 1;
            const int row  = rsel + (it & 1) * 4;
            const __half* src = (tens == 0) ? t_hq : (tens == 1) ? t_lk
                              : (tens == 2) ? t_lq : t_hk;
            float2 f = __half22float2(
                *(const __half2*)(src + (size_t)row * HW + n0 + col2 * 2));
            *(float2*)&tile[tens][row][col2 * 2] = f;
        }
        __syncthreads();

        const float2* q2 = (const float2*)&tile[attn * 2][c][0];
        const float2* k2 = (const float2*)&tile[attn * 2 + 1][d][0];
#pragma unroll 8
        for (int jj = jp * 32; jj < jp * 32 + 32; ++jj) {
            float2 qa = q2[jj], kb = k2[jj];
            acc += qa.x * kb.x + qa.y * kb.y;
        }

        if (t < 32) {
            const float2* rr = (const float2*)&tile[t >> 3][t & 7][0];
#pragma unroll 8
            for (int jj = 0; jj < 64; ++jj) {
                float2 v = rr[jj];
                sq += v.x * v.x + v.y * v.y;
            }
        }
        __syncthreads();
    }

    red[t] = acc;
    __syncthreads();
    float* gp = g_part + (((size_t)chunk * BATCH + b) * HEADS + h) * 160;
    if (t < 128) gp[t] = red[t] + red[t + 128];
    if (t < 32)  gp[128 + t] = sq;
}

// ---------------- Kernel 3b: finalize attention scores ----------------
__global__ void __launch_bounds__(128) attn_final_kernel(
    const float* __restrict__ temp1, const float* __restrict__ temp2)
{
    const int h = blockIdx.x, b = blockIdx.y, t = threadIdx.x;
    __shared__ float invn[32];

    float dot = 0.f;
#pragma unroll
    for (int chv = 0; chv < 8; ++chv)
        dot += g_part[(((size_t)chv * BATCH + b) * HEADS + h) * 160 + t];
    if (t < 32) {
        float sq = 0.f;
#pragma unroll
        for (int chv = 0; chv < 8; ++chv)
            sq += g_part[(((size_t)chv * BATCH + b) * HEADS + h) * 160 + 128 + t];
        invn[t] = 1.f / fmaxf(sqrtf(sq), EPSN);
    }
    __syncthreads();
    const int attn = t >> 6, c = (t >> 3) & 7, d = t & 7;
    float tmp = attn ? __ldg(temp2 + h) : __ldg(temp1 + h);
    float scale = invn[(attn * 2) * 8 + c] * invn[(attn * 2 + 1) * 8 + d] * tmp;
    g_attn[(((size_t)attn * BATCH + b) * HEADS + h) * 64 + c * 8 + d] = dot * scale;
}

// ---------------- Kernel 4: conv fusion + BN + ReLU + softmax ----------------
__global__ void __launch_bounds__(512) fuse_kernel(
    const float* __restrict__ pw, const float* __restrict__ pb,
    const float* __restrict__ gamma, const float* __restrict__ beta,
    const float* __restrict__ mean, const float* __restrict__ var)
{
    const int b = blockIdx.x;
    const int t = threadIdx.x;
    __shared__ float a1s[HEADS * 64];
    __shared__ float a2s[HEADS * 64];

#pragma unroll
    for (int it = 0; it < 8; ++it) {
        int idx = t + it * 512;
        a1s[idx] = g_attn[(size_t)b * 4096 + idx];
        a2s[idx] = g_attn[((size_t)BATCH + b) * 4096 + idx];
    }
    __syncthreads();

    const int ho = t >> 3;
    const int c  = t & 7;
    float f[8] = {0, 0, 0, 0, 0, 0, 0, 0};
    for (int hi = 0; hi < 64; ++hi) {
        float w1 = __ldg(pw + ho * 128 + hi);
        float w2 = __ldg(pw + ho * 128 + 64 + hi);
#pragma unroll
        for (int dd = 0; dd < 8; ++dd) {
            f[dd] += w1 * a1s[hi * 64 + c * 8 + dd];
            f[dd] += w2 * a2s[hi * 64 + c * 8 + dd];
        }
    }
    const float inv_std = rsqrtf(__ldg(var + ho) + EPSBN);
    const float g = __ldg(gamma + ho), bb = __ldg(beta + ho);
    const float mu = __ldg(mean + ho), pbi = __ldg(pb + ho);
#pragma unroll
    for (int dd = 0; dd < 8; ++dd)
        f[dd] = fmaxf((f[dd] + pbi - mu) * inv_std * g + bb, 0.f);

#pragma unroll
    for (int which = 0; which < 2; ++which) {
        const float* as = which ? a2s : a1s;
        float s[8], mx = -1e30f;
#pragma unroll
        for (int dd = 0; dd < 8; ++dd) {
            s[dd] = f[dd] + as[ho * 64 + c * 8 + dd];
            mx = fmaxf(mx, s[dd]);
        }
        float sum = 0.f;
#pragma unroll
        for (int dd = 0; dd < 8; ++dd) { s[dd] = expf(s[dd] - mx); sum += s[dd]; }
        float inv = 1.f / sum;
#pragma unroll
        for (int dd = 0; dd < 8; ++dd)
            g_aw[((size_t)which * BATCH + b) * 4096 + t * 8 + dd] = s[dd] * inv;
    }
}

// ---------------- Kernel 5: output einsum + residuals (float4/fp16 v) ------
__global__ void __launch_bounds__(256) out_kernel(
    const float* __restrict__ hsi, const float* __restrict__ lidar,
    float* __restrict__ out)
{
    const int h   = blockIdx.y;
    const int zz  = blockIdx.z;
    const int mod = zz >> 1;
    const int b   = zz & 1;
    const int t   = threadIdx.x;

    __shared__ float aw[64];
    if (t < 64)
        aw[t] = g_aw[(((size_t)mod * BATCH + b) * HEADS + h) * 64 + t];
    __syncthreads();

    const __half* vsrc = g_dw[mod] + ((size_t)b * C3 + 2 * CDIM + h * CH) * HW;
    const float* xin  = (mod ? lidar : hsi) + ((size_t)b * CDIM + h * CH) * HW;
    float* o = out + (size_t)mod * BATCH * CDIM * HW + ((size_t)b * CDIM + h * CH) * HW;

    const int n = (blockIdx.x * 256 + t) * 4;
    float4 v[8];
#pragma unroll
    for (int dd = 0; dd < 8; ++dd) {
        uint2 raw = *(const uint2*)(vsrc + (size_t)dd * HW + n);
        float2 f01 = __half22float2(*(__half2*)&raw.x);
        float2 f23 = __half22float2(*(__half2*)&raw.y);
        v[dd] = make_float4(f01.x, f01.y, f23.x, f23.y);
    }

#pragma unroll
    for (int c = 0; c < 8; ++c) {
        float4 s = *(const float4*)(xin + (size_t)c * HW + n);
        s.x += v[c].x; s.y += v[c].y; s.z += v[c].z; s.w += v[c].w;
#pragma unroll
        for (int dd = 0; dd < 8; ++dd) {
            const float a = aw[c * 8 + dd];
            s.x += a * v[dd].x; s.y += a * v[dd].y;
            s.z += a * v[dd].z; s.w += a * v[dd].w;
        }
        *(float4*)(o + (size_t)c * HW + n) = s;
    }
}

// ---------------- launch ----------------
extern "C" void kernel_launch(void* const* d_in, const int* in_sizes, int n_in,
                              void* d_out, int out_size)
{
    const float* hsi        = (const float*)d_in[0];
    const float* lidar      = (const float*)d_in[1];
    const float* hsi_qkv_w  = (const float*)d_in[2];
    const float* hsi_qkv_b  = (const float*)d_in[3];
    const float* lidar_qkv_w= (const float*)d_in[4];
    const float* lidar_qkv_b= (const float*)d_in[5];
    const float* hsi_dw_w   = (const float*)d_in[6];
    const float* hsi_dw_b   = (const float*)d_in[7];
    const float* lidar_dw_w = (const float*)d_in[8];
    const float* lidar_dw_b = (const float*)d_in[9];
    const float* temp1      = (const float*)d_in[10];
    const float* temp2      = (const float*)d_in[11];
    const float* proj_w     = (const float*)d_in[12];
    const float* proj_b     = (const float*)d_in[13];
    const float* bn_gamma   = (const float*)d_in[14];
    const float* bn_beta    = (const float*)d_in[15];
    const float* bn_mean    = (const float*)d_in[16];
    const float* bn_var     = (const float*)d_in[17];
    float* out = (float*)d_out;

    static int smem_set = 0;
    if (!smem_set) {
        cudaFuncSetAttribute(qkv_gemm_mma,
                             cudaFuncAttributeMaxDynamicSharedMemorySize, GEMM_SMEM);
        smem_set = 1;
    }

    __half *wf, *xh;
    cudaGetSymbolAddress((void**)&wf, g_wf);
    cudaGetSymbolAddress((void**)&xh, g_xh);

    const int w4 = C3 * CDIM / 4;
    const int x4 = BATCH * CDIM * HW / 4;

    dim3 ggrid(HW / 128, C3 / 128, BATCH);
    dim3 dgrid(4, C3, BATCH);

    // modality 0 (hsi)
    cvt_h<<<(w4 + 255) / 256, 256>>>(hsi_qkv_w, wf, w4);
    cvt_h<<<(x4 + 255) / 256, 256>>>(hsi, xh, x4);
    qkv_gemm_mma<<<ggrid, 256, GEMM_SMEM>>>(hsi_qkv_b);
    dwconv_kernel<<<dgrid, 256>>>(hsi_dw_w, hsi_dw_b, 0);

    // modality 1 (lidar)
    cvt_h<<<(w4 + 255) / 256, 256>>>(lidar_qkv_w, wf, w4);
    cvt_h<<<(x4 + 255) / 256, 256>>>(lidar, xh, x4);
    qkv_gemm_mma<<<ggrid, 256, GEMM_SMEM>>>(lidar_qkv_b);
    dwconv_kernel<<<dgrid, 256>>>(lidar_dw_w, lidar_dw_b, 1);

    attn_partial_kernel<<<dim3(HEADS, BATCH, 8), 256>>>();
    attn_final_kernel<<<dim3(HEADS, BATCH), 128>>>(temp1, temp2);
    fuse_kernel<<<BATCH, 512>>>(proj_w, proj_b, bn_gamma, bn_beta, bn_mean, bn_var);
    out_kernel<<<dim3(HW / 1024, HEADS, BATCH * 2), 256>>>(hsi, lidar, out);
}

// round 11
// speedup vs baseline: 5.3406x; 1.0373x over previous
#include <cuda_runtime.h>
#include <cuda_fp16.h>
#include <cstdint>
#include <math.h>

// ---------------- problem constants ----------------
#define BATCH   2
#define CDIM    512
#define C3      1536
#define HW      16384
#define HEADS   64
#define CH      8
#define EPSN    1e-12f
#define EPSBN   1e-5f

// ---------------- scratch (per-modality where pipelines overlap) -----------
__device__ __half g_qkv[2][BATCH * C3 * HW];             // qkv conv out (fp16)
__device__ __half g_dw[2][BATCH * C3 * HW];              // post-dwconv q/k/v (fp16)
__device__ float g_part[8 * BATCH * HEADS * 160];        // partial dots(128)+sq(32)
__device__ float g_attn[2 * BATCH * HEADS * CH * CH];
__device__ float g_aw[2 * BATCH * HEADS * CH * CH];
__device__ __half g_wf[2][C3 * CDIM];                    // w fp16
__device__ __half g_xh[2][BATCH * CDIM * HW];            // x fp16

// ---------------- PTX helpers (sm_80-era, valid on plain sm_103 target) -----
__device__ __forceinline__ uint32_t smem_u32(const void* p) {
    uint32_t a;
    asm("{ .reg .u64 t; cvta.to.shared.u64 t, %1; cvt.u32.u64 %0, t; }" : "=r"(a) : "l"(p));
    return a;
}
__device__ __forceinline__ void cpasync16(uint32_t saddr, const void* g) {
    asm volatile("cp.async.cg.shared.global [%0], [%1], 16;" :: "r"(saddr), "l"(g));
}
__device__ __forceinline__ void ldsm4(uint32_t addr, uint32_t* r) {
    asm volatile("ldmatrix.sync.aligned.m8n8.x4.shared.b16 {%0,%1,%2,%3}, [%4];"
        : "=r"(r[0]), "=r"(r[1]), "=r"(r[2]), "=r"(r[3]) : "r"(addr));
}
__device__ __forceinline__ void ldsm4t(uint32_t addr, uint32_t* r) {
    asm volatile("ldmatrix.sync.aligned.m8n8.x4.trans.shared.b16 {%0,%1,%2,%3}, [%4];"
        : "=r"(r[0]), "=r"(r[1]), "=r"(r[2]), "=r"(r[3]) : "r"(addr));
}
__device__ __forceinline__ void mma16816(float* c, const uint32_t* a, const uint32_t* b) {
    asm volatile("mma.sync.aligned.m16n8k16.row.col.f32.f16.f16.f32 "
        "{%0,%1,%2,%3}, {%4,%5,%6,%7}, {%8,%9}, {%0,%1,%2,%3};"
        : "+f"(c[0]), "+f"(c[1]), "+f"(c[2]), "+f"(c[3])
        : "r"(a[0]), "r"(a[1]), "r"(a[2]), "r"(a[3]), "r"(b[0]), "r"(b[1]));
}

// ---------------- Kernel 0: fp32 -> fp16 convert ----------------
__global__ void __launch_bounds__(256) cvt_h(
    const float* __restrict__ src, __half* __restrict__ dh, int n4)
{
    int i = blockIdx.x * 256 + threadIdx.x;
    if (i >= n4) return;
    float4 v = ((const float4*)src)[i];
    __half h[4] = { __float2half_rn(v.x), __float2half_rn(v.y),
                    __float2half_rn(v.z), __float2half_rn(v.w) };
    ((uint2*)dh)[i] = *(uint2*)h;
}

// ---------------- Kernel 1: qkv GEMM, fp16 single-product, 3-stage ---------
#define SM_A_STAGE 10240          // 128 rows * 80B (64B data + pad)
#define SM_B_BASE  30720          // after 3 A stages
#define SM_B_STAGE 8704           // 32 rows * 272B (256B data + pad)
#define GEMM_SMEM  56832

__device__ __forceinline__ void gemm_load_stage(
    uint32_t sb, int s, int k0, const __half* wp, const __half* xp, int tid)
{
    uint32_t a_h = sb + s * SM_A_STAGE;
    uint32_t b_h = sb + SM_B_BASE + s * SM_B_STAGE;
#pragma unroll
    for (int it = 0; it < 2; ++it) {
        int cid = tid + it * 256;
        int r = cid >> 2, c = cid & 3;
        cpasync16(a_h + r * 80 + c * 16, wp + (size_t)r * CDIM + k0 + c * 8);
    }
#pragma unroll
    for (int it = 0; it < 2; ++it) {
        int cid = tid + it * 256;
        int r = cid >> 4, c = cid & 15;
        cpasync16(b_h + r * 272 + c * 16, xp + (size_t)(k0 + r) * HW + c * 8);
    }
    asm volatile("cp.async.commit_group;");
}

__global__ void __launch_bounds__(256) qkv_gemm_mma(
    const __half* __restrict__ wf, const __half* __restrict__ xh,
    __half* __restrict__ qkv, const float* __restrict__ bias)
{
    extern __shared__ char smem[];
    const uint32_t sb = smem_u32(smem);
    const int tid = threadIdx.x;
    const int warp = tid >> 5, lid = tid & 31;
    const int n0 = blockIdx.x * 128;
    const int m0 = blockIdx.y * 128;
    const int b  = blockIdx.z;

    const __half* wp = wf + (size_t)m0 * CDIM;
    const __half* xp = xh + (size_t)b * CDIM * HW + n0;

    float acc[4][4][4];
#pragma unroll
    for (int i = 0; i < 4; ++i)
#pragma unroll
        for (int j = 0; j < 4; ++j)
#pragma unroll
            for (int q = 0; q < 4; ++q) acc[i][j][q] = 0.f;

    const int wm = (warp & 1) * 64;
    const int wn = (warp >> 1) * 32;

    gemm_load_stage(sb, 0, 0, wp, xp, tid);
    gemm_load_stage(sb, 1, 32, wp, xp, tid);

    int s = 0;
    for (int ks = 0; ks < 16; ++ks) {
        if (ks == 15) asm volatile("cp.async.wait_group 0;");
        else          asm volatile("cp.async.wait_group 1;");
        __syncthreads();

        if (ks + 2 < 16) {
            int ld = s + 2; if (ld >= 3) ld -= 3;
            gemm_load_stage(sb, ld, (ks + 2) * 32, wp, xp, tid);
        }

        uint32_t a_h = sb + s * SM_A_STAGE;
        uint32_t b_h = sb + SM_B_BASE + s * SM_B_STAGE;

#pragma unroll
        for (int kf = 0; kf < 2; ++kf) {
            uint32_t ah[4][4], bh[2][4];
            const int arow = lid & 15;
            const int acol = kf * 16 + (lid >> 4) * 8;
#pragma unroll
            for (int mf = 0; mf < 4; ++mf) {
                uint32_t off = (uint32_t)((wm + mf * 16 + arow) * 80 + acol * 2);
                ldsm4(a_h + off, ah[mf]);
            }
            const int brow = kf * 16 + (lid & 15);
            const int bcol = (lid >> 4) * 8;
#pragma unroll
            for (int nf2 = 0; nf2 < 2; ++nf2) {
                uint32_t off = (uint32_t)(brow * 272 + (wn + nf2 * 16 + bcol) * 2);
                ldsm4t(b_h + off, bh[nf2]);
            }
#pragma unroll
            for (int mf = 0; mf < 4; ++mf)
#pragma unroll
                for (int nf = 0; nf < 4; ++nf)
                    mma16816(acc[mf][nf], ah[mf], &bh[nf >> 1][(nf & 1) * 2]);
        }
        ++s; if (s == 3) s = 0;
    }

    // epilogue: bias + fp16 stores
    __half* outp = qkv + (size_t)b * C3 * HW;
#pragma unroll
    for (int mf = 0; mf < 4; ++mf) {
        const int r = m0 + wm + mf * 16 + (lid >> 2);
        const float bv0 = __ldg(bias + r);
        const float bv1 = __ldg(bias + r + 8);
#pragma unroll
        for (int nf = 0; nf < 4; ++nf) {
            const int cc = n0 + wn + nf * 8 + 2 * (lid & 3);
            __half2 v0 = __floats2half2_rn(acc[mf][nf][0] + bv0, acc[mf][nf][1] + bv0);
            __half2 v1 = __floats2half2_rn(acc[mf][nf][2] + bv1, acc[mf][nf][3] + bv1);
            *(__half2*)(outp + (size_t)r * HW + cc) = v0;
            *(__half2*)(outp + (size_t)(r + 8) * HW + cc) = v1;
        }
    }
}

// ---------------- Kernel 2: depthwise 3x3, 2 cols/thread, fp16 I/O ---------
__global__ void __launch_bounds__(256) dwconv_kernel(
    const __half* __restrict__ qkv, const float* __restrict__ w,
    const float* __restrict__ bias, __half* __restrict__ dwout)
{
    __shared__ float t[34][132];
    const int c = blockIdx.y, b = blockIdx.z;
    const int r0 = blockIdx.x * 32;
    const int tid = threadIdx.x;
    const __half* xc = qkv + ((size_t)b * C3 + c) * HW;

    for (int idx = tid; idx < 34 * 64; idx += 256) {
        int rr = idx >> 6, jp = idx & 63;
        int gr = r0 - 1 + rr;
        float2 f = make_float2(0.f, 0.f);
        if ((unsigned)gr < 128u)
            f = __half22float2(*(const __half2*)(xc + gr * 128 + jp * 2));
        t[rr][jp * 2 + 1] = f.x;
        t[rr][jp * 2 + 2] = f.y;
    }
    if (tid < 34) { t[tid][0] = 0.f; t[tid][129] = 0.f; }

    float wv[9];
#pragma unroll
    for (int k = 0; k < 9; ++k) wv[k] = __ldg(w + c * 9 + k);
    const float bz = __ldg(bias + c);
    __syncthreads();

    const int p  = (tid & 63) * 2;
    const int rb = (tid >> 6) * 8;
    __half* op = dwout + ((size_t)b * C3 + c) * HW + (size_t)(r0 + rb) * 128 + p;

    float2 A0 = *(const float2*)&t[rb][p];
    float2 A1 = *(const float2*)&t[rb][p + 2];
    float2 B0 = *(const float2*)&t[rb + 1][p];
    float2 B1 = *(const float2*)&t[rb + 1][p + 2];
#pragma unroll
    for (int s = 0; s < 8; ++s) {
        float2 N0 = *(const float2*)&t[rb + 2 + s][p];
        float2 N1 = *(const float2*)&t[rb + 2 + s][p + 2];
        float acc0 = bz + wv[0] * A0.x + wv[1] * A0.y + wv[2] * A1.x
                        + wv[3] * B0.x + wv[4] * B0.y + wv[5] * B1.x
                        + wv[6] * N0.x + wv[7] * N0.y + wv[8] * N1.x;
        float acc1 = bz + wv[0] * A0.y + wv[1] * A1.x + wv[2] * A1.y
                        + wv[3] * B0.y + wv[4] * B1.x + wv[5] * B1.y
                        + wv[6] * N0.y + wv[7] * N1.x + wv[8] * N1.y;
        *(__half2*)(op + (size_t)s * 128) = __floats2half2_rn(acc0, acc1);
        A0 = B0; A1 = B1;
        B0 = N0; B1 = N1;
    }
}

// ---------------- Kernel 3a: partial channel-attn dots + sq over n-chunk ----
__global__ void __launch_bounds__(256) attn_partial_kernel()
{
    const int h = blockIdx.x, b = blockIdx.y, chunk = blockIdx.z;
    const int t = threadIdx.x;

    __shared__ float tile[4][8][132];
    __shared__ float red[256];

    const size_t base = (size_t)b * C3 * HW + (size_t)h * CH * HW;
    const __half* t_hq = g_dw[0] + base;
    const __half* t_lk = g_dw[1] + base + (size_t)CDIM * HW;
    const __half* t_lq = g_dw[1] + base;
    const __half* t_hk = g_dw[0] + base + (size_t)CDIM * HW;

    const int pairattn = t & 127;
    const int jp   = t >> 7;
    const int attn = pairattn >> 6;
    const int c    = (pairattn >> 3) & 7;
    const int d    = pairattn & 7;

    float acc = 0.f, sq = 0.f;
    const int col2 = t & 63;
    const int rsel = t >> 6;

    const int nbeg = chunk * 2048;
    for (int n0 = nbeg; n0 < nbeg + 2048; n0 += 128) {
#pragma unroll
        for (int it = 0; it < 8; ++it) {
            const int tens = it >> 1;
            const int row  = rsel + (it & 1) * 4;
            const __half* src = (tens == 0) ? t_hq : (tens == 1) ? t_lk
                              : (tens == 2) ? t_lq : t_hk;
            float2 f = __half22float2(
                *(const __half2*)(src + (size_t)row * HW + n0 + col2 * 2));
            *(float2*)&tile[tens][row][col2 * 2] = f;
        }
        __syncthreads();

        const float2* q2 = (const float2*)&tile[attn * 2][c][0];
        const float2* k2 = (const float2*)&tile[attn * 2 + 1][d][0];
#pragma unroll 8
        for (int jj = jp * 32; jj < jp * 32 + 32; ++jj) {
            float2 qa = q2[jj], kb = k2[jj];
            acc += qa.x * kb.x + qa.y * kb.y;
        }

        if (t < 32) {
            const float2* rr = (const float2*)&tile[t >> 3][t & 7][0];
#pragma unroll 8
            for (int jj = 0; jj < 64; ++jj) {
                float2 v = rr[jj];
                sq += v.x * v.x + v.y * v.y;
            }
        }
        __syncthreads();
    }

    red[t] = acc;
    __syncthreads();
    float* gp = g_part + (((size_t)chunk * BATCH + b) * HEADS + h) * 160;
    if (t < 128) gp[t] = red[t] + red[t + 128];
    if (t < 32)  gp[128 + t] = sq;
}

// ---------------- Kernel 3b: finalize attention scores ----------------
__global__ void __launch_bounds__(128) attn_final_kernel(
    const float* __restrict__ temp1, const float* __restrict__ temp2)
{
    const int h = blockIdx.x, b = blockIdx.y, t = threadIdx.x;
    __shared__ float invn[32];

    float dot = 0.f;
#pragma unroll
    for (int chv = 0; chv < 8; ++chv)
        dot += g_part[(((size_t)chv * BATCH + b) * HEADS + h) * 160 + t];
    if (t < 32) {
        float sq = 0.f;
#pragma unroll
        for (int chv = 0; chv < 8; ++chv)
            sq += g_part[(((size_t)chv * BATCH + b) * HEADS + h) * 160 + 128 + t];
        invn[t] = 1.f / fmaxf(sqrtf(sq), EPSN);
    }
    __syncthreads();
    const int attn = t >> 6, c = (t >> 3) & 7, d = t & 7;
    float tmp = attn ? __ldg(temp2 + h) : __ldg(temp1 + h);
    float scale = invn[(attn * 2) * 8 + c] * invn[(attn * 2 + 1) * 8 + d] * tmp;
    g_attn[(((size_t)attn * BATCH + b) * HEADS + h) * 64 + c * 8 + d] = dot * scale;
}

// ---------------- Kernel 4: conv fusion + BN + ReLU + softmax ----------------
__global__ void __launch_bounds__(512) fuse_kernel(
    const float* __restrict__ pw, const float* __restrict__ pb,
    const float* __restrict__ gamma, const float* __restrict__ beta,
    const float* __restrict__ mean, const float* __restrict__ var)
{
    const int b = blockIdx.x;
    const int t = threadIdx.x;
    __shared__ float a1s[HEADS * 64];
    __shared__ float a2s[HEADS * 64];

#pragma unroll
    for (int it = 0; it < 8; ++it) {
        int idx = t + it * 512;
        a1s[idx] = g_attn[(size_t)b * 4096 + idx];
        a2s[idx] = g_attn[((size_t)BATCH + b) * 4096 + idx];
    }
    __syncthreads();

    const int ho = t >> 3;
    const int c  = t & 7;
    float f[8] = {0, 0, 0, 0, 0, 0, 0, 0};
    for (int hi = 0; hi < 64; ++hi) {
        float w1 = __ldg(pw + ho * 128 + hi);
        float w2 = __ldg(pw + ho * 128 + 64 + hi);
#pragma unroll
        for (int dd = 0; dd < 8; ++dd) {
            f[dd] += w1 * a1s[hi * 64 + c * 8 + dd];
            f[dd] += w2 * a2s[hi * 64 + c * 8 + dd];
        }
    }
    const float inv_std = rsqrtf(__ldg(var + ho) + EPSBN);
    const float g = __ldg(gamma + ho), bb = __ldg(beta + ho);
    const float mu = __ldg(mean + ho), pbi = __ldg(pb + ho);
#pragma unroll
    for (int dd = 0; dd < 8; ++dd)
        f[dd] = fmaxf((f[dd] + pbi - mu) * inv_std * g + bb, 0.f);

#pragma unroll
    for (int which = 0; which < 2; ++which) {
        const float* as = which ? a2s : a1s;
        float s[8], mx = -1e30f;
#pragma unroll
        for (int dd = 0; dd < 8; ++dd) {
            s[dd] = f[dd] + as[ho * 64 + c * 8 + dd];
            mx = fmaxf(mx, s[dd]);
        }
        float sum = 0.f;
#pragma unroll
        for (int dd = 0; dd < 8; ++dd) { s[dd] = expf(s[dd] - mx); sum += s[dd]; }
        float inv = 1.f / sum;
#pragma unroll
        for (int dd = 0; dd < 8; ++dd)
            g_aw[((size_t)which * BATCH + b) * 4096 + t * 8 + dd] = s[dd] * inv;
    }
}

// ---------------- Kernel 5: output einsum + residuals (float4/fp16 v) ------
__global__ void __launch_bounds__(256) out_kernel(
    const float* __restrict__ hsi, const float* __restrict__ lidar,
    float* __restrict__ out)
{
    const int h   = blockIdx.y;
    const int zz  = blockIdx.z;
    const int mod = zz >> 1;
    const int b   = zz & 1;
    const int t   = threadIdx.x;

    __shared__ float aw[64];
    if (t < 64)
        aw[t] = g_aw[(((size_t)mod * BATCH + b) * HEADS + h) * 64 + t];
    __syncthreads();

    const __half* vsrc = g_dw[mod] + ((size_t)b * C3 + 2 * CDIM + h * CH) * HW;
    const float* xin  = (mod ? lidar : hsi) + ((size_t)b * CDIM + h * CH) * HW;
    float* o = out + (size_t)mod * BATCH * CDIM * HW + ((size_t)b * CDIM + h * CH) * HW;

    const int n = (blockIdx.x * 256 + t) * 4;
    float4 v[8];
#pragma unroll
    for (int dd = 0; dd < 8; ++dd) {
        uint2 raw = *(const uint2*)(vsrc + (size_t)dd * HW + n);
        float2 f01 = __half22float2(*(__half2*)&raw.x);
        float2 f23 = __half22float2(*(__half2*)&raw.y);
        v[dd] = make_float4(f01.x, f01.y, f23.x, f23.y);
    }

#pragma unroll
    for (int c = 0; c < 8; ++c) {
        float4 s = *(const float4*)(xin + (size_t)c * HW + n);
        s.x += v[c].x; s.y += v[c].y; s.z += v[c].z; s.w += v[c].w;
#pragma unroll
        for (int dd = 0; dd < 8; ++dd) {
            const float a = aw[c * 8 + dd];
            s.x += a * v[dd].x; s.y += a * v[dd].y;
            s.z += a * v[dd].z; s.w += a * v[dd].w;
        }
        *(float4*)(o + (size_t)c * HW + n) = s;
    }
}

// ---------------- launch ----------------
extern "C" void kernel_launch(void* const* d_in, const int* in_sizes, int n_in,
                              void* d_out, int out_size)
{
    const float* hsi        = (const float*)d_in[0];
    const float* lidar      = (const float*)d_in[1];
    const float* hsi_qkv_w  = (const float*)d_in[2];
    const float* hsi_qkv_b  = (const float*)d_in[3];
    const float* lidar_qkv_w= (const float*)d_in[4];
    const float* lidar_qkv_b= (const float*)d_in[5];
    const float* hsi_dw_w   = (const float*)d_in[6];
    const float* hsi_dw_b   = (const float*)d_in[7];
    const float* lidar_dw_w = (const float*)d_in[8];
    const float* lidar_dw_b = (const float*)d_in[9];
    const float* temp1      = (const float*)d_in[10];
    const float* temp2      = (const float*)d_in[11];
    const float* proj_w     = (const float*)d_in[12];
    const float* proj_b     = (const float*)d_in[13];
    const float* bn_gamma   = (const float*)d_in[14];
    const float* bn_beta    = (const float*)d_in[15];
    const float* bn_mean    = (const float*)d_in[16];
    const float* bn_var     = (const float*)d_in[17];
    float* out = (float*)d_out;

    static int inited = 0;
    static cudaStream_t s1;
    static cudaEvent_t evFork, evJoin;
    if (!inited) {
        cudaFuncSetAttribute(qkv_gemm_mma,
                             cudaFuncAttributeMaxDynamicSharedMemorySize, GEMM_SMEM);
        cudaStreamCreateWithFlags(&s1, cudaStreamNonBlocking);
        cudaEventCreateWithFlags(&evFork, cudaEventDisableTiming);
        cudaEventCreateWithFlags(&evJoin, cudaEventDisableTiming);
        inited = 1;
    }

    __half *wf0, *wf1, *xh0, *xh1, *qk0, *qk1;
    cudaGetSymbolAddress((void**)&wf0, g_wf);   wf1 = wf0 + (size_t)C3 * CDIM;
    cudaGetSymbolAddress((void**)&xh0, g_xh);   xh1 = xh0 + (size_t)BATCH * CDIM * HW;
    cudaGetSymbolAddress((void**)&qk0, g_qkv);  qk1 = qk0 + (size_t)BATCH * C3 * HW;
    __half *dw0, *dw1;
    cudaGetSymbolAddress((void**)&dw0, g_dw);   dw1 = dw0 + (size_t)BATCH * C3 * HW;

    const int w4 = C3 * CDIM / 4;
    const int x4 = BATCH * CDIM * HW / 4;

    dim3 ggrid(HW / 128, C3 / 128, BATCH);
    dim3 dgrid(4, C3, BATCH);

    // fork: lidar pipeline on s1, hsi pipeline on the capture (default) stream
    cudaEventRecord(evFork, 0);
    cudaStreamWaitEvent(s1, evFork, 0);

    // hsi (default stream)
    cvt_h<<<(w4 + 255) / 256, 256>>>(hsi_qkv_w, wf0, w4);
    cvt_h<<<(x4 + 255) / 256, 256>>>(hsi, xh0, x4);
    qkv_gemm_mma<<<ggrid, 256, GEMM_SMEM>>>(wf0, xh0, qk0, hsi_qkv_b);
    dwconv_kernel<<<dgrid, 256>>>(qk0, hsi_dw_w, hsi_dw_b, dw0);

    // lidar (s1)
    cvt_h<<<(w4 + 255) / 256, 256, 0, s1>>>(lidar_qkv_w, wf1, w4);
    cvt_h<<<(x4 + 255) / 256, 256, 0, s1>>>(lidar, xh1, x4);
    qkv_gemm_mma<<<ggrid, 256, GEMM_SMEM, s1>>>(wf1, xh1, qk1, lidar_qkv_b);
    dwconv_kernel<<<dgrid, 256, 0, s1>>>(qk1, lidar_dw_w, lidar_dw_b, dw1);

    // join
    cudaEventRecord(evJoin, s1);
    cudaStreamWaitEvent(0, evJoin, 0);

    attn_partial_kernel<<<dim3(HEADS, BATCH, 8), 256>>>();
    attn_final_kernel<<<dim3(HEADS, BATCH), 128>>>(temp1, temp2);
    fuse_kernel<<<BATCH, 512>>>(proj_w, proj_b, bn_gamma, bn_beta, bn_mean, bn_var);
    out_kernel<<<dim3(HW / 1024, HEADS, BATCH * 2), 256>>>(hsi, lidar, out);
}